// round 12
// baseline (speedup 1.0000x reference)
#include <cuda_runtime.h>

typedef unsigned int       u32;
typedef unsigned long long u64;

__constant__ float cW1c[36*64];   // W1 compacted to 36 rows (zero obs rows dropped)
__constant__ float cW2[64*64];

static __device__ __forceinline__ u64 ffma2(u64 a, u64 b, u64 c){
    u64 d; asm("fma.rn.f32x2 %0, %1, %2, %3;" : "=l"(d) : "l"(a), "l"(b), "l"(c)); return d;
}
static __device__ __forceinline__ u64 fadd2(u64 a, u64 b){
    u64 d; asm("add.rn.f32x2 %0, %1, %2;" : "=l"(d) : "l"(a), "l"(b)); return d;
}
static __device__ __forceinline__ u64 pack2(float x){
    u64 r; asm("mov.b64 %0, {%1, %1};" : "=l"(r) : "f"(x)); return r;
}
static __device__ __forceinline__ u64 pack2b(float x, float y){
    u64 r; asm("mov.b64 %0, {%1, %2};" : "=l"(r) : "f"(x), "f"(y)); return r;
}
static __device__ __forceinline__ float2 unpack2(u64 v){
    float lo, hi; asm("mov.b64 {%0, %1}, %2;" : "=f"(lo), "=f"(hi) : "l"(v)); return make_float2(lo, hi);
}
static __device__ __forceinline__ u32 smaddr(const void* p){
    u32 a; asm("{ .reg .u64 t; cvta.to.shared.u64 t, %1; cvt.u32.u64 %0, t; }" : "=r"(a) : "l"(p)); return a;
}
static __device__ __forceinline__ void cp16(u32 dst, const void* src){
    asm volatile("cp.async.cg.shared.global [%0], [%1], 16;" :: "r"(dst), "l"(src));
}
#define CP_COMMIT() asm volatile("cp.async.commit_group;" ::: "memory")
#define CP_WAIT0()  asm volatile("cp.async.wait_group 0;" ::: "memory")

// ---------------- smem layout (float offsets) ----------------
#define SHR   0        // SOBS [36][132] / SH1 [64][132] / PF buffer = 8448
#define XST   8448     // 16 batches * 144 floats = 2304
#define SB1   10752    // 64
#define SB2   10816    // 64
#define SWD   10880    // 64 float2 = 128
#define SCC   11008    // 2 (+2 pad)
#define SMEM_FLOATS 11012   // 44048 B

#define BPB   128
#define TILEB 128
#define LDA   132

// one k-step: 4 batches (1 LDS.128) x 16 outputs; W from __constant__ (warp-uniform addr)
#define K_STEPC(AP, CW, WOFF, KK) do { \
    ulonglong2 Av = *(const ulonglong2*)((AP) + (KK)*LDA); \
    float4 Wa = *(const float4*)&(CW)[(KK)*64 + (WOFF)]; \
    float4 Wb = *(const float4*)&(CW)[(KK)*64 + (WOFF) + 4]; \
    float4 Wc = *(const float4*)&(CW)[(KK)*64 + (WOFF) + 8]; \
    float4 Wd = *(const float4*)&(CW)[(KK)*64 + (WOFF) + 12]; \
    u64 a0 = Av.x, a1 = Av.y; \
    u64 w; \
    w = pack2(Wa.x); acc[0]  = ffma2(a0,w,acc[0]);  acc[1]  = ffma2(a1,w,acc[1]); \
    w = pack2(Wa.y); acc[2]  = ffma2(a0,w,acc[2]);  acc[3]  = ffma2(a1,w,acc[3]); \
    w = pack2(Wa.z); acc[4]  = ffma2(a0,w,acc[4]);  acc[5]  = ffma2(a1,w,acc[5]); \
    w = pack2(Wa.w); acc[6]  = ffma2(a0,w,acc[6]);  acc[7]  = ffma2(a1,w,acc[7]); \
    w = pack2(Wb.x); acc[8]  = ffma2(a0,w,acc[8]);  acc[9]  = ffma2(a1,w,acc[9]); \
    w = pack2(Wb.y); acc[10] = ffma2(a0,w,acc[10]); acc[11] = ffma2(a1,w,acc[11]); \
    w = pack2(Wb.z); acc[12] = ffma2(a0,w,acc[12]); acc[13] = ffma2(a1,w,acc[13]); \
    w = pack2(Wb.w); acc[14] = ffma2(a0,w,acc[14]); acc[15] = ffma2(a1,w,acc[15]); \
    w = pack2(Wc.x); acc[16] = ffma2(a0,w,acc[16]); acc[17] = ffma2(a1,w,acc[17]); \
    w = pack2(Wc.y); acc[18] = ffma2(a0,w,acc[18]); acc[19] = ffma2(a1,w,acc[19]); \
    w = pack2(Wc.z); acc[20] = ffma2(a0,w,acc[20]); acc[21] = ffma2(a1,w,acc[21]); \
    w = pack2(Wc.w); acc[22] = ffma2(a0,w,acc[22]); acc[23] = ffma2(a1,w,acc[23]); \
    w = pack2(Wd.x); acc[24] = ffma2(a0,w,acc[24]); acc[25] = ffma2(a1,w,acc[25]); \
    w = pack2(Wd.y); acc[26] = ffma2(a0,w,acc[26]); acc[27] = ffma2(a1,w,acc[27]); \
    w = pack2(Wd.z); acc[28] = ffma2(a0,w,acc[28]); acc[29] = ffma2(a1,w,acc[29]); \
    w = pack2(Wd.w); acc[30] = ffma2(a0,w,acc[30]); acc[31] = ffma2(a1,w,acc[31]); \
} while(0)

__global__ __launch_bounds__(BPB, 4) void maddpg_v12_kernel(
    const float* __restrict__ x,
    const float* __restrict__ b1,
    const float* __restrict__ b2,
    const float* __restrict__ W3, const float* __restrict__ b3,
    const int* __restrict__ idx,
    float* __restrict__ out, int B)
{
    extern __shared__ float sm[];
    __shared__ int sIdx[8];
    __shared__ int sActive[5];
    const int tid  = threadIdx.x;
    const int wid  = tid >> 5;       // warp -> output group 16*wid (warp-uniform!)
    const int lane = tid & 31;       // lane -> batches 4*lane..4*lane+3
    const u32 smb = smaddr(sm);
    const int b0  = blockIdx.x * TILEB;
    const long nf4 = (long)B * 35;
    const int woff = 16*wid;

    // staging map: warp handles 4 batches of the 16-batch wave
    const int slb = 4*wid + (lane >> 3);
    const int sq  = lane & 7;
    const u32 sdst_base = smb + (u32)((XST + slb*144) * 4);

    // ---- issue stage wave 0 ----
    {
        long gb = ((long)(b0 + slb)) * 35;
        #pragma unroll
        for (int j = 0; j < 5; j++){
            int f4 = sq + 8*j;
            if (f4 < 35){
                long gi = gb + f4;
                if (gi < nf4) cp16(sdst_base + (u32)(f4*16), (const float4*)x + gi);
            }
        }
        CP_COMMIT();
    }
    if (tid < 8)  sIdx[tid] = idx[tid];
    if (tid < 5)  sActive[tid] = 0;
    if (tid < 16) ((float4*)(sm + SB1))[tid] = ((const float4*)b1)[tid];
    else if (tid < 32) ((float4*)(sm + SB2))[tid-16] = ((const float4*)b2)[tid-16];
    if (tid < 64){
        float a1 = W3[tid*5+1], a2 = W3[tid*5+2], a3 = W3[tid*5+3], a4 = W3[tid*5+4];
        ((float2*)(sm + SWD))[tid] = make_float2(a1 - a2, a3 - a4);
    }
    if (tid == 0) *(float2*)(sm + SCC) = make_float2(b3[1]-b3[2], b3[3]-b3[4]);

    // obs-build role map: warp-uniform, half-warp sub-roles
    const int half = lane >> 4;
    const int olb  = lane & 15;

    // ---- 8 staging waves of 16 batches ----
    #pragma unroll 1
    for (int w = 0; w < 8; w++){
        CP_WAIT0();
        __syncthreads();
        {
            const float* xb = sm + XST + olb*144;
            const float p0 = xb[0], p1 = xb[1];
            float* ob = sm + SHR + (w*16 + olb);
            if (wid == 0){
                if (half == 0){
                    ob[0*LDA] = p0;    ob[1*LDA] = p1;    ob[2*LDA] = xb[2];
                    ob[3*LDA] = xb[3]; ob[4*LDA] = xb[4];
                } else {
                    const float* r = xb + (sIdx[7] + 10)*7;   // obstacle 4
                    float dx = r[0]-p0, dy = r[1]-p1;
                    bool in = (dx*dx + dy*dy) < 0.0225f;
                    if (in) sActive[4] = 1;
                    ob[31*LDA] = in ? dx   : 0.0f;
                    ob[32*LDA] = in ? dy   : 0.0f;
                    ob[33*LDA] = in ? r[2] : 0.0f;
                    ob[34*LDA] = in ? r[3] : 0.0f;
                    ob[35*LDA] = in ? r[4] : 0.0f;
                }
            } else if (wid == 1){
                if (half == 0){
                    #pragma unroll
                    for (int m = 0; m < 2; m++){
                        const float* r = xb + sIdx[m]*7;
                        ob[(5+2*m)*LDA] = (r[5] + r[0]) - p0;
                        ob[(6+2*m)*LDA] = (r[6] + r[1]) - p1;
                    }
                } else {
                    const float* r = xb + sIdx[2]*7;
                    ob[9*LDA]  = (r[5] + r[0]) - p0;
                    ob[10*LDA] = (r[6] + r[1]) - p1;
                }
            } else {
                int m = (wid - 2)*2 + half;                   // obstacles 0..3
                const float* r = xb + (sIdx[3+m] + 10)*7;
                float dx = r[0]-p0, dy = r[1]-p1;
                bool in = (dx*dx + dy*dy) < 0.0225f;
                if (in) sActive[m] = 1;
                int kb = 11 + 5*m;
                ob[(kb+0)*LDA] = in ? dx   : 0.0f;
                ob[(kb+1)*LDA] = in ? dy   : 0.0f;
                ob[(kb+2)*LDA] = in ? r[2] : 0.0f;
                ob[(kb+3)*LDA] = in ? r[3] : 0.0f;
                ob[(kb+4)*LDA] = in ? r[4] : 0.0f;
            }
        }
        __syncthreads();
        if (w < 7){
            long gb = ((long)(b0 + (w+1)*16 + slb)) * 35;
            #pragma unroll
            for (int j = 0; j < 5; j++){
                int f4 = sq + 8*j;
                if (f4 < 35){
                    long gi = gb + f4;
                    if (gi < nf4) cp16(sdst_base + (u32)(f4*16), (const float4*)x + gi);
                }
            }
            CP_COMMIT();
        }
    }

    int act0 = sActive[0], act1 = sActive[1], act2 = sActive[2],
        act3 = sActive[3], act4 = sActive[4];

    // ---- GEMM1: [128 x 36] * [36 x 64], W from constant ----
    u64 acc[32];
    #pragma unroll
    for (int i = 0; i < 32; i++) acc[i] = 0ull;
    {
        const float* ap = sm + SHR + 4*lane;
        #pragma unroll
        for (int k = 0; k < 11; k++) K_STEPC(ap, cW1c, woff, k);
        if (act0){
            #pragma unroll
            for (int k = 11; k < 16; k++) K_STEPC(ap, cW1c, woff, k);
        }
        if (act1){
            #pragma unroll
            for (int k = 16; k < 21; k++) K_STEPC(ap, cW1c, woff, k);
        }
        if (act2){
            #pragma unroll
            for (int k = 21; k < 26; k++) K_STEPC(ap, cW1c, woff, k);
        }
        if (act3){
            #pragma unroll
            for (int k = 26; k < 31; k++) K_STEPC(ap, cW1c, woff, k);
        }
        if (act4){
            #pragma unroll
            for (int k = 31; k < 36; k++) K_STEPC(ap, cW1c, woff, k);
        }
    }
    __syncthreads();     // SOBS reads complete

    // ---- epilogue 1: relu(acc + b1) -> SH1 rows ----
    #pragma unroll
    for (int o = 0; o < 16; o++){
        float bv = sm[SB1 + 16*wid + o];
        float2 f0 = unpack2(acc[2*o]);
        float2 f1 = unpack2(acc[2*o+1]);
        float4 v;
        v.x = fmaxf(f0.x + bv, 0.0f); v.y = fmaxf(f0.y + bv, 0.0f);
        v.z = fmaxf(f1.x + bv, 0.0f); v.w = fmaxf(f1.y + bv, 0.0f);
        *(float4*)(sm + SHR + (16*wid + o)*LDA + 4*lane) = v;
    }
    __syncthreads();     // SH1 visible

    // ---- GEMM2: [128 x 64] * [64 x 64], W from constant ----
    #pragma unroll
    for (int i = 0; i < 32; i++) acc[i] = 0ull;
    {
        const float* ap = sm + SHR + 4*lane;
        #pragma unroll 8
        for (int k = 0; k < 64; k++) K_STEPC(ap, cW2, woff, k);
    }
    __syncthreads();     // SH1 reads done; SHR free for PF buffer

    // ---- register fold over this thread's 16 outputs ----
    {
        u64 pfx[2], pfy[2];
        pfx[0] = pfx[1] = pfy[0] = pfy[1] = 0ull;
        #pragma unroll
        for (int o = 0; o < 16; o++){
            float bv = sm[SB2 + 16*wid + o];
            float2 wdv = ((const float2*)(sm + SWD))[16*wid + o];
            u64 wx = pack2(wdv.x), wy = pack2(wdv.y);
            #pragma unroll
            for (int h = 0; h < 2; h++){
                float2 f = unpack2(acc[2*o + h]);
                u64 rr = pack2b(fmaxf(f.x + bv, 0.0f), fmaxf(f.y + bv, 0.0f));
                pfx[h] = ffma2(rr, wx, pfx[h]);
                pfy[h] = ffma2(rr, wy, pfy[h]);
            }
        }
        ulonglong2* pf = (ulonglong2*)(sm + SHR);
        #pragma unroll
        for (int h = 0; h < 2; h++){
            ulonglong2 v; v.x = pfx[h]; v.y = pfy[h];
            pf[wid*64 + 2*lane + h] = v;
        }
    }
    __syncthreads();

    // ---- reduce over 4 warps, scale, clip, store ----
    if (tid < 64){
        const ulonglong2* pf = (const ulonglong2*)(sm + SHR);
        float2 cc = *(const float2*)(sm + SCC);
        u64 ax = pack2(cc.x), ay = pack2(cc.y);
        #pragma unroll
        for (int t = 0; t < 4; t++){
            ulonglong2 v = pf[t*64 + tid];
            ax = fadd2(ax, v.x);
            ay = fadd2(ay, v.y);
        }
        float2 rx = unpack2(ax);
        float2 ry = unpack2(ay);
        float v0 = rx.x * 0.1f, v1 = ry.x * 0.1f;
        float v2 = rx.y * 0.1f, v3 = ry.y * 0.1f;
        if (fabsf(v0) > 1.0f) v0 = copysignf(2.0f, v0);
        if (fabsf(v1) > 1.0f) v1 = copysignf(2.0f, v1);
        if (fabsf(v2) > 1.0f) v2 = copysignf(2.0f, v2);
        if (fabsf(v3) > 1.0f) v3 = copysignf(2.0f, v3);
        int b = b0 + 2*tid;
        if (b < B){
            float4 o4; o4.x = v0; o4.y = v1; o4.z = v2; o4.w = v3;
            ((float4*)out)[(b0 >> 1) + tid] = o4;
        }
    }
}

extern "C" void kernel_launch(void* const* d_in, const int* in_sizes, int n_in,
                              void* d_out, int out_size)
{
    const float* x  = (const float*)d_in[0];
    const float* W1 = (const float*)d_in[1];
    const float* b1 = (const float*)d_in[2];
    const float* W2 = (const float*)d_in[3];
    const float* b2 = (const float*)d_in[4];
    const float* W3 = (const float*)d_in[5];
    const float* b3 = (const float*)d_in[6];
    const int*  idx = (const int*)d_in[7];

    const int B = in_sizes[0] / 140;
    const int blocks = (B + TILEB - 1) / TILEB;
    const size_t smem = SMEM_FLOATS * sizeof(float);

    // W1 compacted into constant memory: keep rows {0-6, 8-9, 11-12, 14-38}
    cudaMemcpyToSymbolAsync(cW1c, W1,        7*64*sizeof(float),  0,                cudaMemcpyDeviceToDevice, 0);
    cudaMemcpyToSymbolAsync(cW1c, W1+8*64,   2*64*sizeof(float),  7*64*sizeof(float),  cudaMemcpyDeviceToDevice, 0);
    cudaMemcpyToSymbolAsync(cW1c, W1+11*64,  2*64*sizeof(float),  9*64*sizeof(float),  cudaMemcpyDeviceToDevice, 0);
    cudaMemcpyToSymbolAsync(cW1c, W1+14*64, 25*64*sizeof(float), 11*64*sizeof(float),  cudaMemcpyDeviceToDevice, 0);
    cudaMemcpyToSymbolAsync(cW2,  W2, 64*64*sizeof(float), 0, cudaMemcpyDeviceToDevice, 0);

    cudaFuncSetAttribute(maddpg_v12_kernel,
                         cudaFuncAttributeMaxDynamicSharedMemorySize, (int)smem);

    maddpg_v12_kernel<<<blocks, BPB, smem>>>(x, b1, b2, W3, b3, idx,
                                             (float*)d_out, B);
}

// round 13
// speedup vs baseline: 1.5706x; 1.5706x over previous
#include <cuda_runtime.h>

typedef unsigned int       u32;
typedef unsigned long long u64;

static __device__ __forceinline__ u64 ffma2(u64 a, u64 b, u64 c){
    u64 d; asm("fma.rn.f32x2 %0, %1, %2, %3;" : "=l"(d) : "l"(a), "l"(b), "l"(c)); return d;
}
static __device__ __forceinline__ u64 fadd2(u64 a, u64 b){
    u64 d; asm("add.rn.f32x2 %0, %1, %2;" : "=l"(d) : "l"(a), "l"(b)); return d;
}
static __device__ __forceinline__ u64 pack2(float x){
    u64 r; asm("mov.b64 %0, {%1, %1};" : "=l"(r) : "f"(x)); return r;
}
static __device__ __forceinline__ u64 pack2b(float x, float y){
    u64 r; asm("mov.b64 %0, {%1, %2};" : "=l"(r) : "f"(x), "f"(y)); return r;
}
static __device__ __forceinline__ float2 unpack2(u64 v){
    float lo, hi; asm("mov.b64 {%0, %1}, %2;" : "=f"(lo), "=f"(hi) : "l"(v)); return make_float2(lo, hi);
}
static __device__ __forceinline__ u32 smaddr(const void* p){
    u32 a; asm("{ .reg .u64 t; cvta.to.shared.u64 t, %1; cvt.u32.u64 %0, t; }" : "=r"(a) : "l"(p)); return a;
}
static __device__ __forceinline__ void cp16(u32 dst, const void* src){
    asm volatile("cp.async.cg.shared.global [%0], [%1], 16;" :: "r"(dst), "l"(src));
}
#define CP_COMMIT() asm volatile("cp.async.commit_group;" ::: "memory")
#define CP_WAIT0()  asm volatile("cp.async.wait_group 0;" ::: "memory")

// ---------------- smem layout (float offsets) ----------------
#define SW1   0        // W1 compact [36][64]                 = 2304
#define SW2   2304     // W2 [64][64]                         = 4096
#define SHR   6400     // SOBS [36][132] / SH1 [64][132] / PF = 8448
#define XST   14848    // 32 batches * 148 floats             = 4736 (stride 148: 4-way max conflicts)
#define SB1   19584    // 64
#define SB2   19648    // 64
#define SWD   19712    // 64 float2 = 128
#define SCC   19840    // 2 (+2 pad)
#define SMEM_FLOATS 19844   // 79376 B ... too big for 4 CTAs? 4*79376=317KB > 227KB!

// NOTE: weights must fit too. Rebalance: W1c+W2 = 6400 floats. Total above is 79KB -> only 2 CTAs.
// Fix: overlap W region with nothing, but shrink XST usage by keeping W2 load deferred (v8 trick):
// WRG region holds W1 (2304) during GEMM1, W2 (4096) after. XST shares tail as in v8.
#undef SW1
#undef SW2
#undef SHR
#undef XST
#undef SB1
#undef SB2
#undef SWD
#undef SCC
#undef SMEM_FLOATS
#define SHR   0        // SOBS [36][132] / SH1 [64][132] / PF = 8448
#define WRG   8448     // W1 compact [36][64]=2304 -> W2 [64][64]=4096 (overwritten after GEMM1)
#define XST   12544    // 32 batches * 148 floats = 4736  (starts at WRG+4096, past W1's 2304)
#define SB1   17280    // 64
#define SB2   17344    // 64
#define SWD   17408    // 128
#define SCC   17536    // 2 (+2 pad)
#define SMEM_FLOATS 17540   // 70160 B -> 3 CTAs/SM (210KB); XST dies before W2 arrives

#define BPB   128
#define TILEB 128
#define LDA   132

// one k-step: 4 batches (1 LDS.128, conflict-free) x 16 outputs per thread. acc[2*o+h]
#define K_STEP(AP, WP, KK) do { \
    ulonglong2 Av = *(const ulonglong2*)((AP) + (KK)*LDA); \
    float4 Wa = *(const float4*)((WP) + (KK)*64); \
    float4 Wb = *(const float4*)((WP) + (KK)*64 + 4); \
    float4 Wc = *(const float4*)((WP) + (KK)*64 + 8); \
    float4 Wd = *(const float4*)((WP) + (KK)*64 + 12); \
    u64 a0 = Av.x, a1 = Av.y; \
    u64 w; \
    w = pack2(Wa.x); acc[0]  = ffma2(a0,w,acc[0]);  acc[1]  = ffma2(a1,w,acc[1]); \
    w = pack2(Wa.y); acc[2]  = ffma2(a0,w,acc[2]);  acc[3]  = ffma2(a1,w,acc[3]); \
    w = pack2(Wa.z); acc[4]  = ffma2(a0,w,acc[4]);  acc[5]  = ffma2(a1,w,acc[5]); \
    w = pack2(Wa.w); acc[6]  = ffma2(a0,w,acc[6]);  acc[7]  = ffma2(a1,w,acc[7]); \
    w = pack2(Wb.x); acc[8]  = ffma2(a0,w,acc[8]);  acc[9]  = ffma2(a1,w,acc[9]); \
    w = pack2(Wb.y); acc[10] = ffma2(a0,w,acc[10]); acc[11] = ffma2(a1,w,acc[11]); \
    w = pack2(Wb.z); acc[12] = ffma2(a0,w,acc[12]); acc[13] = ffma2(a1,w,acc[13]); \
    w = pack2(Wb.w); acc[14] = ffma2(a0,w,acc[14]); acc[15] = ffma2(a1,w,acc[15]); \
    w = pack2(Wc.x); acc[16] = ffma2(a0,w,acc[16]); acc[17] = ffma2(a1,w,acc[17]); \
    w = pack2(Wc.y); acc[18] = ffma2(a0,w,acc[18]); acc[19] = ffma2(a1,w,acc[19]); \
    w = pack2(Wc.z); acc[20] = ffma2(a0,w,acc[20]); acc[21] = ffma2(a1,w,acc[21]); \
    w = pack2(Wc.w); acc[22] = ffma2(a0,w,acc[22]); acc[23] = ffma2(a1,w,acc[23]); \
    w = pack2(Wd.x); acc[24] = ffma2(a0,w,acc[24]); acc[25] = ffma2(a1,w,acc[25]); \
    w = pack2(Wd.y); acc[26] = ffma2(a0,w,acc[26]); acc[27] = ffma2(a1,w,acc[27]); \
    w = pack2(Wd.z); acc[28] = ffma2(a0,w,acc[28]); acc[29] = ffma2(a1,w,acc[29]); \
    w = pack2(Wd.w); acc[30] = ffma2(a0,w,acc[30]); acc[31] = ffma2(a1,w,acc[31]); \
} while(0)

__global__ __launch_bounds__(BPB, 3) void maddpg_v13_kernel(
    const float* __restrict__ x,
    const float* __restrict__ W1, const float* __restrict__ b1,
    const float* __restrict__ W2, const float* __restrict__ b2,
    const float* __restrict__ W3, const float* __restrict__ b3,
    const int* __restrict__ idx,
    float* __restrict__ out, int B)
{
    extern __shared__ float sm[];
    __shared__ int sIdx[8];
    __shared__ int sActive[5];
    const int tid  = threadIdx.x;
    const int wid  = tid >> 5;       // warp -> output group 16*wid / obs role
    const int lane = tid & 31;       // lane -> batches 4*lane / obs batch
    const u32 smb = smaddr(sm);
    const int b0  = blockIdx.x * TILEB;
    const long nf4 = (long)B * 35;

    // staging map: warp stages 8 batches of the 32-batch wave; thread does 9 cp16
    const int slb = 8*wid + (lane >> 2);   // local batch 0..31
    const int sq  = lane & 3;              // float4 phase
    const u32 sdst_base = smb + (u32)((XST + slb*148) * 4);

    // ---- issue stage wave 0 (32 batches) ----
    {
        long gb = ((long)(b0 + slb)) * 35;
        #pragma unroll
        for (int j = 0; j < 9; j++){
            int f4 = sq + 4*j;
            if (f4 < 35){
                long gi = gb + f4;
                if (gi < nf4) cp16(sdst_base + (u32)(f4*16), (const float4*)x + gi);
            }
        }
        CP_COMMIT();
    }
    if (tid < 8)  sIdx[tid] = idx[tid];
    if (tid < 5)  sActive[tid] = 0;
    // W1 compacted to 36 rows into WRG
    #pragma unroll
    for (int j = 0; j < 5; j++){
        int i = j*BPB + tid;
        if (i < 576){
            int ck = i >> 4, nq = i & 15;
            int o;
            if (ck < 5)       o = ck;
            else if (ck < 11) { int m = (ck-5) >> 1; o = 5 + 3*m + ((ck-5)&1); }
            else              o = 14 + (ck - 11);
            ((float4*)(sm + WRG))[i] = ((const float4*)W1)[o*16 + nq];
        }
    }
    if (tid < 16) ((float4*)(sm + SB1))[tid] = ((const float4*)b1)[tid];
    else if (tid < 32) ((float4*)(sm + SB2))[tid-16] = ((const float4*)b2)[tid-16];
    if (tid < 64){
        float a1 = W3[tid*5+1], a2 = W3[tid*5+2], a3 = W3[tid*5+3], a4 = W3[tid*5+4];
        ((float2*)(sm + SWD))[tid] = make_float2(a1 - a2, a3 - a4);
    }
    if (tid == 0) *(float2*)(sm + SCC) = make_float2(b3[1]-b3[2], b3[3]-b3[4]);

    // ---- 4 staging waves of 32 batches; obs role = warp (uniform), batch = lane ----
    #pragma unroll 1
    for (int w = 0; w < 4; w++){
        CP_WAIT0();
        __syncthreads();
        {
            const float* xb = sm + XST + lane*148;
            const float p0 = xb[0], p1 = xb[1];
            float* ob = sm + SHR + (w*32 + lane);   // column; lane-consecutive => coalesced STS
            if (wid == 0){
                ob[0*LDA] = p0;    ob[1*LDA] = p1;    ob[2*LDA] = xb[2];
                ob[3*LDA] = xb[3]; ob[4*LDA] = xb[4];
                const float* r = xb + (sIdx[7] + 10)*7;       // obstacle 4
                float dx = r[0]-p0, dy = r[1]-p1;
                bool in = (dx*dx + dy*dy) < 0.0225f;
                if (in) sActive[4] = 1;
                ob[31*LDA] = in ? dx   : 0.0f;
                ob[32*LDA] = in ? dy   : 0.0f;
                ob[33*LDA] = in ? r[2] : 0.0f;
                ob[34*LDA] = in ? r[3] : 0.0f;
                ob[35*LDA] = in ? r[4] : 0.0f;
            } else if (wid == 1){
                #pragma unroll
                for (int m = 0; m < 3; m++){
                    const float* r = xb + sIdx[m]*7;
                    ob[(5+2*m)*LDA] = (r[5] + r[0]) - p0;
                    ob[(6+2*m)*LDA] = (r[6] + r[1]) - p1;
                }
            } else {
                #pragma unroll
                for (int mm = 0; mm < 2; mm++){
                    int m = (wid-2)*2 + mm;                   // obstacles 0..3
                    const float* r = xb + (sIdx[3+m] + 10)*7;
                    float dx = r[0]-p0, dy = r[1]-p1;
                    bool in = (dx*dx + dy*dy) < 0.0225f;
                    if (in) sActive[m] = 1;
                    int kb = 11 + 5*m;
                    ob[(kb+0)*LDA] = in ? dx   : 0.0f;
                    ob[(kb+1)*LDA] = in ? dy   : 0.0f;
                    ob[(kb+2)*LDA] = in ? r[2] : 0.0f;
                    ob[(kb+3)*LDA] = in ? r[3] : 0.0f;
                    ob[(kb+4)*LDA] = in ? r[4] : 0.0f;
                }
            }
        }
        __syncthreads();
        if (w < 3){
            long gb = ((long)(b0 + (w+1)*32 + slb)) * 35;
            #pragma unroll
            for (int j = 0; j < 9; j++){
                int f4 = sq + 4*j;
                if (f4 < 35){
                    long gi = gb + f4;
                    if (gi < nf4) cp16(sdst_base + (u32)(f4*16), (const float4*)x + gi);
                }
            }
            CP_COMMIT();
        }
    }

    int act0 = sActive[0], act1 = sActive[1], act2 = sActive[2],
        act3 = sActive[3], act4 = sActive[4];

    // ---- GEMM1: [128 x 36] * [36 x 64] ----
    u64 acc[32];
    #pragma unroll
    for (int i = 0; i < 32; i++) acc[i] = 0ull;
    {
        const float* ap = sm + SHR + 4*lane;
        const float* wp = sm + WRG + 16*wid;
        #pragma unroll
        for (int k = 0; k < 11; k++) K_STEP(ap, wp, k);
        if (act0){
            #pragma unroll
            for (int k = 11; k < 16; k++) K_STEP(ap, wp, k);
        }
        if (act1){
            #pragma unroll
            for (int k = 16; k < 21; k++) K_STEP(ap, wp, k);
        }
        if (act2){
            #pragma unroll
            for (int k = 21; k < 26; k++) K_STEP(ap, wp, k);
        }
        if (act3){
            #pragma unroll
            for (int k = 26; k < 31; k++) K_STEP(ap, wp, k);
        }
        if (act4){
            #pragma unroll
            for (int k = 31; k < 36; k++) K_STEP(ap, wp, k);
        }
    }
    __syncthreads();     // W1 + SOBS + XST fully consumed

    // ---- issue W2 over the WRG region (W1 + XST head are dead now) ----
    #pragma unroll
    for (int j = 0; j < 8; j++)
        cp16(smb + (u32)((WRG + (j*BPB + tid)*4) * 4), (const float4*)W2 + j*BPB + tid);
    CP_COMMIT();

    // ---- epilogue 1: relu(acc + b1) -> SH1 rows ----
    #pragma unroll
    for (int o = 0; o < 16; o++){
        float bv = sm[SB1 + 16*wid + o];
        float2 f0 = unpack2(acc[2*o]);
        float2 f1 = unpack2(acc[2*o+1]);
        float4 v;
        v.x = fmaxf(f0.x + bv, 0.0f); v.y = fmaxf(f0.y + bv, 0.0f);
        v.z = fmaxf(f1.x + bv, 0.0f); v.w = fmaxf(f1.y + bv, 0.0f);
        *(float4*)(sm + SHR + (16*wid + o)*LDA + 4*lane) = v;
    }
    CP_WAIT0();
    __syncthreads();     // SH1 visible + W2 landed

    // ---- GEMM2: [128 x 64] * [64 x 64] ----
    #pragma unroll
    for (int i = 0; i < 32; i++) acc[i] = 0ull;
    {
        const float* ap = sm + SHR + 4*lane;
        const float* wp = sm + WRG + 16*wid;
        #pragma unroll 8
        for (int k = 0; k < 64; k++) K_STEP(ap, wp, k);
    }
    __syncthreads();     // SH1 reads done; SHR free for PF buffer

    // ---- register fold over this thread's 16 outputs ----
    {
        u64 pfx[2], pfy[2];
        pfx[0] = pfx[1] = pfy[0] = pfy[1] = 0ull;
        #pragma unroll
        for (int o = 0; o < 16; o++){
            float bv = sm[SB2 + 16*wid + o];
            float2 wdv = ((const float2*)(sm + SWD))[16*wid + o];
            u64 wx = pack2(wdv.x), wy = pack2(wdv.y);
            #pragma unroll
            for (int h = 0; h < 2; h++){
                float2 f = unpack2(acc[2*o + h]);
                u64 rr = pack2b(fmaxf(f.x + bv, 0.0f), fmaxf(f.y + bv, 0.0f));
                pfx[h] = ffma2(rr, wx, pfx[h]);
                pfy[h] = ffma2(rr, wy, pfy[h]);
            }
        }
        ulonglong2* pf = (ulonglong2*)(sm + SHR);
        #pragma unroll
        for (int h = 0; h < 2; h++){
            ulonglong2 v; v.x = pfx[h]; v.y = pfy[h];
            pf[wid*64 + 2*lane + h] = v;
        }
    }
    __syncthreads();

    // ---- reduce over 4 warps, scale, clip, store ----
    if (tid < 64){
        const ulonglong2* pf = (const ulonglong2*)(sm + SHR);
        float2 cc = *(const float2*)(sm + SCC);
        u64 ax = pack2(cc.x), ay = pack2(cc.y);
        #pragma unroll
        for (int t = 0; t < 4; t++){
            ulonglong2 v = pf[t*64 + tid];
            ax = fadd2(ax, v.x);
            ay = fadd2(ay, v.y);
        }
        float2 rx = unpack2(ax);
        float2 ry = unpack2(ay);
        float v0 = rx.x * 0.1f, v1 = ry.x * 0.1f;
        float v2 = rx.y * 0.1f, v3 = ry.y * 0.1f;
        if (fabsf(v0) > 1.0f) v0 = copysignf(2.0f, v0);
        if (fabsf(v1) > 1.0f) v1 = copysignf(2.0f, v1);
        if (fabsf(v2) > 1.0f) v2 = copysignf(2.0f, v2);
        if (fabsf(v3) > 1.0f) v3 = copysignf(2.0f, v3);
        int b = b0 + 2*tid;
        if (b < B){
            float4 o4; o4.x = v0; o4.y = v1; o4.z = v2; o4.w = v3;
            ((float4*)out)[(b0 >> 1) + tid] = o4;
        }
    }
}

extern "C" void kernel_launch(void* const* d_in, const int* in_sizes, int n_in,
                              void* d_out, int out_size)
{
    const float* x  = (const float*)d_in[0];
    const float* W1 = (const float*)d_in[1];
    const float* b1 = (const float*)d_in[2];
    const float* W2 = (const float*)d_in[3];
    const float* b2 = (const float*)d_in[4];
    const float* W3 = (const float*)d_in[5];
    const float* b3 = (const float*)d_in[6];
    const int*  idx = (const int*)d_in[7];

    const int B = in_sizes[0] / 140;
    const int blocks = (B + TILEB - 1) / TILEB;
    const size_t smem = SMEM_FLOATS * sizeof(float);

    cudaFuncSetAttribute(maddpg_v13_kernel,
                         cudaFuncAttributeMaxDynamicSharedMemorySize, (int)smem);

    maddpg_v13_kernel<<<blocks, BPB, smem>>>(x, W1, b1, W2, b2, W3, b3, idx,
                                             (float*)d_out, B);
}

// round 14
// speedup vs baseline: 1.6065x; 1.0229x over previous
#include <cuda_runtime.h>

typedef unsigned int       u32;
typedef unsigned long long u64;

static __device__ __forceinline__ u64 ffma2(u64 a, u64 b, u64 c){
    u64 d; asm("fma.rn.f32x2 %0, %1, %2, %3;" : "=l"(d) : "l"(a), "l"(b), "l"(c)); return d;
}
static __device__ __forceinline__ u64 fadd2(u64 a, u64 b){
    u64 d; asm("add.rn.f32x2 %0, %1, %2;" : "=l"(d) : "l"(a), "l"(b)); return d;
}
static __device__ __forceinline__ u64 pack2(float x){
    u64 r; asm("mov.b64 %0, {%1, %1};" : "=l"(r) : "f"(x)); return r;
}
static __device__ __forceinline__ u64 pack2b(float x, float y){
    u64 r; asm("mov.b64 %0, {%1, %2};" : "=l"(r) : "f"(x), "f"(y)); return r;
}
static __device__ __forceinline__ float2 unpack2(u64 v){
    float lo, hi; asm("mov.b64 {%0, %1}, %2;" : "=f"(lo), "=f"(hi) : "l"(v)); return make_float2(lo, hi);
}
static __device__ __forceinline__ u32 smaddr(const void* p){
    u32 a; asm("{ .reg .u64 t; cvta.to.shared.u64 t, %1; cvt.u32.u64 %0, t; }" : "=r"(a) : "l"(p)); return a;
}
static __device__ __forceinline__ void cp16(u32 dst, const void* src){
    asm volatile("cp.async.cg.shared.global [%0], [%1], 16;" :: "r"(dst), "l"(src));
}
#define CP_COMMIT() asm volatile("cp.async.commit_group;" ::: "memory")
#define CP_WAIT0()  asm volatile("cp.async.wait_group 0;" ::: "memory")

// ---------------- smem layout (float offsets) ----------------
// WRG holds W1-compact (2304 floats) during staging+GEMM1, then W2 (4096) after.
// XST (16 batches x 148 floats = 2368) overlaps WRG's tail + 576 beyond; it is
// dead by the time the deferred W2 cp.async lands (issued after GEMM1's last W1 read).
#define SHR   0        // SOBS [36][132] / SH1 [64][132] / PF = 8448
#define WRG   8448     // W1 compact ends at 10752; W2 spans 8448..12544 (later)
#define XST   10752    // 16 * 148 = 2368 -> ends 13120
#define SB1   13120    // 64
#define SB2   13184    // 64
#define SWD   13248    // 64 float2 = 128
#define SCC   13376    // 2 (+2 pad)
#define SMEM_FLOATS 13380   // 53520 B -> 4 CTAs/SM

#define BPB   128
#define TILEB 128
#define LDA   132      // SOBS/SH1 row stride
#define XLD   148      // XST row stride (2-way max bank conflicts on scalar reads)

// one k-step: 4 batches (1 LDS.128, conflict-free) x 16 outputs per thread. acc[2*o+h]
#define K_STEP(AP, WP, KK) do { \
    ulonglong2 Av = *(const ulonglong2*)((AP) + (KK)*LDA); \
    float4 Wa = *(const float4*)((WP) + (KK)*64); \
    float4 Wb = *(const float4*)((WP) + (KK)*64 + 4); \
    float4 Wc = *(const float4*)((WP) + (KK)*64 + 8); \
    float4 Wd = *(const float4*)((WP) + (KK)*64 + 12); \
    u64 a0 = Av.x, a1 = Av.y; \
    u64 w; \
    w = pack2(Wa.x); acc[0]  = ffma2(a0,w,acc[0]);  acc[1]  = ffma2(a1,w,acc[1]); \
    w = pack2(Wa.y); acc[2]  = ffma2(a0,w,acc[2]);  acc[3]  = ffma2(a1,w,acc[3]); \
    w = pack2(Wa.z); acc[4]  = ffma2(a0,w,acc[4]);  acc[5]  = ffma2(a1,w,acc[5]); \
    w = pack2(Wa.w); acc[6]  = ffma2(a0,w,acc[6]);  acc[7]  = ffma2(a1,w,acc[7]); \
    w = pack2(Wb.x); acc[8]  = ffma2(a0,w,acc[8]);  acc[9]  = ffma2(a1,w,acc[9]); \
    w = pack2(Wb.y); acc[10] = ffma2(a0,w,acc[10]); acc[11] = ffma2(a1,w,acc[11]); \
    w = pack2(Wb.z); acc[12] = ffma2(a0,w,acc[12]); acc[13] = ffma2(a1,w,acc[13]); \
    w = pack2(Wb.w); acc[14] = ffma2(a0,w,acc[14]); acc[15] = ffma2(a1,w,acc[15]); \
    w = pack2(Wc.x); acc[16] = ffma2(a0,w,acc[16]); acc[17] = ffma2(a1,w,acc[17]); \
    w = pack2(Wc.y); acc[18] = ffma2(a0,w,acc[18]); acc[19] = ffma2(a1,w,acc[19]); \
    w = pack2(Wc.z); acc[20] = ffma2(a0,w,acc[20]); acc[21] = ffma2(a1,w,acc[21]); \
    w = pack2(Wc.w); acc[22] = ffma2(a0,w,acc[22]); acc[23] = ffma2(a1,w,acc[23]); \
    w = pack2(Wd.x); acc[24] = ffma2(a0,w,acc[24]); acc[25] = ffma2(a1,w,acc[25]); \
    w = pack2(Wd.y); acc[26] = ffma2(a0,w,acc[26]); acc[27] = ffma2(a1,w,acc[27]); \
    w = pack2(Wd.z); acc[28] = ffma2(a0,w,acc[28]); acc[29] = ffma2(a1,w,acc[29]); \
    w = pack2(Wd.w); acc[30] = ffma2(a0,w,acc[30]); acc[31] = ffma2(a1,w,acc[31]); \
} while(0)

__global__ __launch_bounds__(BPB, 4) void maddpg_v14_kernel(
    const float* __restrict__ x,
    const float* __restrict__ W1, const float* __restrict__ b1,
    const float* __restrict__ W2, const float* __restrict__ b2,
    const float* __restrict__ W3, const float* __restrict__ b3,
    const int* __restrict__ idx,
    float* __restrict__ out, int B)
{
    extern __shared__ float sm[];
    __shared__ int sIdx[8];
    __shared__ int sActive[5];
    const int tid  = threadIdx.x;
    const int wid  = tid >> 5;       // warp -> output group 16*wid (warp-uniform W addr)
    const int lane = tid & 31;       // lane -> batches 4*lane..4*lane+3
    const u32 smb = smaddr(sm);
    const int b0  = blockIdx.x * TILEB;
    const long nf4 = (long)B * 35;

    // staging map: warp handles 4 batches of the 16-batch wave
    const int slb = 4*wid + (lane >> 3);
    const int sq  = lane & 7;
    const u32 sdst_base = smb + (u32)((XST + slb*XLD) * 4);

    // ---- issue stage wave 0 ----
    {
        long gb = ((long)(b0 + slb)) * 35;
        #pragma unroll
        for (int j = 0; j < 5; j++){
            int f4 = sq + 8*j;
            if (f4 < 35){
                long gi = gb + f4;
                if (gi < nf4) cp16(sdst_base + (u32)(f4*16), (const float4*)x + gi);
            }
        }
        CP_COMMIT();
    }
    if (tid < 8)  sIdx[tid] = idx[tid];
    if (tid < 5)  sActive[tid] = 0;
    // W1 compacted to 36 rows (structurally-zero obs rows dropped)
    #pragma unroll
    for (int j = 0; j < 5; j++){
        int i = j*BPB + tid;
        if (i < 576){
            int ck = i >> 4, nq = i & 15;
            int o;
            if (ck < 5)       o = ck;
            else if (ck < 11) { int m = (ck-5) >> 1; o = 5 + 3*m + ((ck-5)&1); }
            else              o = 14 + (ck - 11);
            ((float4*)(sm + WRG))[i] = ((const float4*)W1)[o*16 + nq];
        }
    }
    if (tid < 16) ((float4*)(sm + SB1))[tid] = ((const float4*)b1)[tid];
    else if (tid < 32) ((float4*)(sm + SB2))[tid-16] = ((const float4*)b2)[tid-16];
    if (tid < 64){
        float a1 = W3[tid*5+1], a2 = W3[tid*5+2], a3 = W3[tid*5+3], a4 = W3[tid*5+4];
        ((float2*)(sm + SWD))[tid] = make_float2(a1 - a2, a3 - a4);
    }
    if (tid == 0) *(float2*)(sm + SCC) = make_float2(b3[1]-b3[2], b3[3]-b3[4]);

    // obs-build role map: warp-uniform main role, half-warp sub-roles
    const int half = lane >> 4;
    const int olb  = lane & 15;

    // ---- 8 staging waves of 16 batches ----
    #pragma unroll 1
    for (int w = 0; w < 8; w++){
        CP_WAIT0();
        __syncthreads();
        {
            const float* xb = sm + XST + olb*XLD;
            const float p0 = xb[0], p1 = xb[1];
            float* ob = sm + SHR + (w*16 + olb);
            if (wid == 0){
                if (half == 0){
                    ob[0*LDA] = p0;    ob[1*LDA] = p1;    ob[2*LDA] = xb[2];
                    ob[3*LDA] = xb[3]; ob[4*LDA] = xb[4];
                } else {
                    const float* r = xb + (sIdx[7] + 10)*7;   // obstacle 4
                    float dx = r[0]-p0, dy = r[1]-p1;
                    bool in = (dx*dx + dy*dy) < 0.0225f;
                    if (in) sActive[4] = 1;
                    ob[31*LDA] = in ? dx   : 0.0f;
                    ob[32*LDA] = in ? dy   : 0.0f;
                    ob[33*LDA] = in ? r[2] : 0.0f;
                    ob[34*LDA] = in ? r[3] : 0.0f;
                    ob[35*LDA] = in ? r[4] : 0.0f;
                }
            } else if (wid == 1){
                if (half == 0){
                    #pragma unroll
                    for (int m = 0; m < 2; m++){
                        const float* r = xb + sIdx[m]*7;
                        ob[(5+2*m)*LDA] = (r[5] + r[0]) - p0;
                        ob[(6+2*m)*LDA] = (r[6] + r[1]) - p1;
                    }
                } else {
                    const float* r = xb + sIdx[2]*7;
                    ob[9*LDA]  = (r[5] + r[0]) - p0;
                    ob[10*LDA] = (r[6] + r[1]) - p1;
                }
            } else {
                int m = (wid - 2)*2 + half;                   // obstacles 0..3
                const float* r = xb + (sIdx[3+m] + 10)*7;
                float dx = r[0]-p0, dy = r[1]-p1;
                bool in = (dx*dx + dy*dy) < 0.0225f;
                if (in) sActive[m] = 1;
                int kb = 11 + 5*m;
                ob[(kb+0)*LDA] = in ? dx   : 0.0f;
                ob[(kb+1)*LDA] = in ? dy   : 0.0f;
                ob[(kb+2)*LDA] = in ? r[2] : 0.0f;
                ob[(kb+3)*LDA] = in ? r[3] : 0.0f;
                ob[(kb+4)*LDA] = in ? r[4] : 0.0f;
            }
        }
        __syncthreads();
        if (w < 7){
            long gb = ((long)(b0 + (w+1)*16 + slb)) * 35;
            #pragma unroll
            for (int j = 0; j < 5; j++){
                int f4 = sq + 8*j;
                if (f4 < 35){
                    long gi = gb + f4;
                    if (gi < nf4) cp16(sdst_base + (u32)(f4*16), (const float4*)x + gi);
                }
            }
            CP_COMMIT();
        }
    }

    int act0 = sActive[0], act1 = sActive[1], act2 = sActive[2],
        act3 = sActive[3], act4 = sActive[4];

    // ---- GEMM1: [128 x 36] * [36 x 64] ----
    u64 acc[32];
    #pragma unroll
    for (int i = 0; i < 32; i++) acc[i] = 0ull;
    {
        const float* ap = sm + SHR + 4*lane;
        const float* wp = sm + WRG + 16*wid;
        #pragma unroll
        for (int k = 0; k < 11; k++) K_STEP(ap, wp, k);
        if (act0){
            #pragma unroll
            for (int k = 11; k < 16; k++) K_STEP(ap, wp, k);
        }
        if (act1){
            #pragma unroll
            for (int k = 16; k < 21; k++) K_STEP(ap, wp, k);
        }
        if (act2){
            #pragma unroll
            for (int k = 21; k < 26; k++) K_STEP(ap, wp, k);
        }
        if (act3){
            #pragma unroll
            for (int k = 26; k < 31; k++) K_STEP(ap, wp, k);
        }
        if (act4){
            #pragma unroll
            for (int k = 31; k < 36; k++) K_STEP(ap, wp, k);
        }
    }
    __syncthreads();     // W1 + SOBS + XST fully consumed

    // ---- issue W2 over the WRG/XST region ----
    #pragma unroll
    for (int j = 0; j < 8; j++)
        cp16(smb + (u32)((WRG + (j*BPB + tid)*4) * 4), (const float4*)W2 + j*BPB + tid);
    CP_COMMIT();

    // ---- epilogue 1: relu(acc + b1) -> SH1 rows ----
    #pragma unroll
    for (int o = 0; o < 16; o++){
        float bv = sm[SB1 + 16*wid + o];
        float2 f0 = unpack2(acc[2*o]);
        float2 f1 = unpack2(acc[2*o+1]);
        float4 v;
        v.x = fmaxf(f0.x + bv, 0.0f); v.y = fmaxf(f0.y + bv, 0.0f);
        v.z = fmaxf(f1.x + bv, 0.0f); v.w = fmaxf(f1.y + bv, 0.0f);
        *(float4*)(sm + SHR + (16*wid + o)*LDA + 4*lane) = v;
    }
    CP_WAIT0();
    __syncthreads();     // SH1 visible + W2 landed

    // ---- GEMM2: [128 x 64] * [64 x 64] ----
    #pragma unroll
    for (int i = 0; i < 32; i++) acc[i] = 0ull;
    {
        const float* ap = sm + SHR + 4*lane;
        const float* wp = sm + WRG + 16*wid;
        #pragma unroll 8
        for (int k = 0; k < 64; k++) K_STEP(ap, wp, k);
    }
    __syncthreads();     // SH1 reads done; SHR free for PF buffer

    // ---- register fold over this thread's 16 outputs ----
    {
        u64 pfx[2], pfy[2];
        pfx[0] = pfx[1] = pfy[0] = pfy[1] = 0ull;
        #pragma unroll
        for (int o = 0; o < 16; o++){
            float bv = sm[SB2 + 16*wid + o];
            float2 wdv = ((const float2*)(sm + SWD))[16*wid + o];
            u64 wx = pack2(wdv.x), wy = pack2(wdv.y);
            #pragma unroll
            for (int h = 0; h < 2; h++){
                float2 f = unpack2(acc[2*o + h]);
                u64 rr = pack2b(fmaxf(f.x + bv, 0.0f), fmaxf(f.y + bv, 0.0f));
                pfx[h] = ffma2(rr, wx, pfx[h]);
                pfy[h] = ffma2(rr, wy, pfy[h]);
            }
        }
        ulonglong2* pf = (ulonglong2*)(sm + SHR);
        #pragma unroll
        for (int h = 0; h < 2; h++){
            ulonglong2 v; v.x = pfx[h]; v.y = pfy[h];
            pf[wid*64 + 2*lane + h] = v;
        }
    }
    __syncthreads();

    // ---- reduce over 4 warps, scale, clip, store ----
    if (tid < 64){
        const ulonglong2* pf = (const ulonglong2*)(sm + SHR);
        float2 cc = *(const float2*)(sm + SCC);
        u64 ax = pack2(cc.x), ay = pack2(cc.y);
        #pragma unroll
        for (int t = 0; t < 4; t++){
            ulonglong2 v = pf[t*64 + tid];
            ax = fadd2(ax, v.x);
            ay = fadd2(ay, v.y);
        }
        float2 rx = unpack2(ax);
        float2 ry = unpack2(ay);
        float v0 = rx.x * 0.1f, v1 = ry.x * 0.1f;
        float v2 = rx.y * 0.1f, v3 = ry.y * 0.1f;
        if (fabsf(v0) > 1.0f) v0 = copysignf(2.0f, v0);
        if (fabsf(v1) > 1.0f) v1 = copysignf(2.0f, v1);
        if (fabsf(v2) > 1.0f) v2 = copysignf(2.0f, v2);
        if (fabsf(v3) > 1.0f) v3 = copysignf(2.0f, v3);
        int b = b0 + 2*tid;
        if (b < B){
            float4 o4; o4.x = v0; o4.y = v1; o4.z = v2; o4.w = v3;
            ((float4*)out)[(b0 >> 1) + tid] = o4;
        }
    }
}

extern "C" void kernel_launch(void* const* d_in, const int* in_sizes, int n_in,
                              void* d_out, int out_size)
{
    const float* x  = (const float*)d_in[0];
    const float* W1 = (const float*)d_in[1];
    const float* b1 = (const float*)d_in[2];
    const float* W2 = (const float*)d_in[3];
    const float* b2 = (const float*)d_in[4];
    const float* W3 = (const float*)d_in[5];
    const float* b3 = (const float*)d_in[6];
    const int*  idx = (const int*)d_in[7];

    const int B = in_sizes[0] / 140;
    const int blocks = (B + TILEB - 1) / TILEB;
    const size_t smem = SMEM_FLOATS * sizeof(float);

    cudaFuncSetAttribute(maddpg_v14_kernel,
                         cudaFuncAttributeMaxDynamicSharedMemorySize, (int)smem);

    maddpg_v14_kernel<<<blocks, BPB, smem>>>(x, W1, b1, W2, b2, W3, b3, idx,
                                             (float*)d_out, B);
}

// round 15
// speedup vs baseline: 1.7003x; 1.0584x over previous
#include <cuda_runtime.h>

typedef unsigned int       u32;
typedef unsigned long long u64;

static __device__ __forceinline__ u64 ffma2(u64 a, u64 b, u64 c){
    u64 d; asm("fma.rn.f32x2 %0, %1, %2, %3;" : "=l"(d) : "l"(a), "l"(b), "l"(c)); return d;
}
static __device__ __forceinline__ u64 fadd2(u64 a, u64 b){
    u64 d; asm("add.rn.f32x2 %0, %1, %2;" : "=l"(d) : "l"(a), "l"(b)); return d;
}
static __device__ __forceinline__ u64 pack2(float x){
    u64 r; asm("mov.b64 %0, {%1, %1};" : "=l"(r) : "f"(x)); return r;
}
static __device__ __forceinline__ u64 pack2b(float x, float y){
    u64 r; asm("mov.b64 %0, {%1, %2};" : "=l"(r) : "f"(x), "f"(y)); return r;
}
static __device__ __forceinline__ float2 unpack2(u64 v){
    float lo, hi; asm("mov.b64 {%0, %1}, %2;" : "=f"(lo), "=f"(hi) : "l"(v)); return make_float2(lo, hi);
}
static __device__ __forceinline__ u32 smaddr(const void* p){
    u32 a; asm("{ .reg .u64 t; cvta.to.shared.u64 t, %1; cvt.u32.u64 %0, t; }" : "=r"(a) : "l"(p)); return a;
}
static __device__ __forceinline__ void cp16(u32 dst, const void* src){
    asm volatile("cp.async.cg.shared.global [%0], [%1], 16;" :: "r"(dst), "l"(src));
}
#define CP_COMMIT() asm volatile("cp.async.commit_group;" ::: "memory")
#define CP_WAIT0()  asm volatile("cp.async.wait_group 0;" ::: "memory")

// ---------------- smem layout (float offsets) ----------------
#define SHR   0        // SOBS [36][132] / SH1 [64][132] / PF = 8448
#define WRG   8448     // W1 compact (2304) -> W2 (4096) after GEMM1
#define XST   10752    // 16 batches * 148 floats = 2368 -> ends 13120
#define SB1   13120    // 64
#define SB2   13184    // 64
#define SWDX  13248    // 32 u64 = 64 floats (x-diff pairs)
#define SWDY  13312    // 32 u64 = 64 floats (y-diff pairs)
#define SCC   13376    // float2 (+2 pad)
#define SMEM_FLOATS 13380   // 53520 B -> 4 CTAs/SM

#define BPB   128
#define TILEB 128
#define LDA   132      // SOBS/SH1 row stride
#define XLD   148      // XST row stride

// one k-step: 4 batch scalars (1 LDS.128 + 4 pack2) x 8 weight-pairs (4 LDS.128, NO movs)
// acc[8*b + op] = outputs (2op, 2op+1) for batch 4*lane+b
#define K_STEP(AP, WP, KK) do { \
    float4 a4 = *(const float4*)((AP) + (KK)*LDA); \
    ulonglong2 Wq0 = *(const ulonglong2*)((WP) + (KK)*64); \
    ulonglong2 Wq1 = *(const ulonglong2*)((WP) + (KK)*64 + 4); \
    ulonglong2 Wq2 = *(const ulonglong2*)((WP) + (KK)*64 + 8); \
    ulonglong2 Wq3 = *(const ulonglong2*)((WP) + (KK)*64 + 12); \
    u64 a0 = pack2(a4.x), a1 = pack2(a4.y), a2 = pack2(a4.z), a3 = pack2(a4.w); \
    acc[0]  = ffma2(a0, Wq0.x, acc[0]);  acc[8]  = ffma2(a1, Wq0.x, acc[8]); \
    acc[16] = ffma2(a2, Wq0.x, acc[16]); acc[24] = ffma2(a3, Wq0.x, acc[24]); \
    acc[1]  = ffma2(a0, Wq0.y, acc[1]);  acc[9]  = ffma2(a1, Wq0.y, acc[9]); \
    acc[17] = ffma2(a2, Wq0.y, acc[17]); acc[25] = ffma2(a3, Wq0.y, acc[25]); \
    acc[2]  = ffma2(a0, Wq1.x, acc[2]);  acc[10] = ffma2(a1, Wq1.x, acc[10]); \
    acc[18] = ffma2(a2, Wq1.x, acc[18]); acc[26] = ffma2(a3, Wq1.x, acc[26]); \
    acc[3]  = ffma2(a0, Wq1.y, acc[3]);  acc[11] = ffma2(a1, Wq1.y, acc[11]); \
    acc[19] = ffma2(a2, Wq1.y, acc[19]); acc[27] = ffma2(a3, Wq1.y, acc[27]); \
    acc[4]  = ffma2(a0, Wq2.x, acc[4]);  acc[12] = ffma2(a1, Wq2.x, acc[12]); \
    acc[20] = ffma2(a2, Wq2.x, acc[20]); acc[28] = ffma2(a3, Wq2.x, acc[28]); \
    acc[5]  = ffma2(a0, Wq2.y, acc[5]);  acc[13] = ffma2(a1, Wq2.y, acc[13]); \
    acc[21] = ffma2(a2, Wq2.y, acc[21]); acc[29] = ffma2(a3, Wq2.y, acc[29]); \
    acc[6]  = ffma2(a0, Wq3.x, acc[6]);  acc[14] = ffma2(a1, Wq3.x, acc[14]); \
    acc[22] = ffma2(a2, Wq3.x, acc[22]); acc[30] = ffma2(a3, Wq3.x, acc[30]); \
    acc[7]  = ffma2(a0, Wq3.y, acc[7]);  acc[15] = ffma2(a1, Wq3.y, acc[15]); \
    acc[23] = ffma2(a2, Wq3.y, acc[23]); acc[31] = ffma2(a3, Wq3.y, acc[31]); \
} while(0)

__global__ __launch_bounds__(BPB, 4) void maddpg_v15_kernel(
    const float* __restrict__ x,
    const float* __restrict__ W1, const float* __restrict__ b1,
    const float* __restrict__ W2, const float* __restrict__ b2,
    const float* __restrict__ W3, const float* __restrict__ b3,
    const int* __restrict__ idx,
    float* __restrict__ out, int B)
{
    extern __shared__ float sm[];
    __shared__ int sIdx[8];
    __shared__ int sActive[5];
    const int tid  = threadIdx.x;
    const int wid  = tid >> 5;       // warp -> output group 16*wid
    const int lane = tid & 31;       // lane -> batches 4*lane..4*lane+3
    const u32 smb = smaddr(sm);
    const int b0  = blockIdx.x * TILEB;
    const long nf4 = (long)B * 35;

    // staging map: warp handles 4 batches of the 16-batch wave
    const int slb = 4*wid + (lane >> 3);
    const int sq  = lane & 7;
    const u32 sdst_base = smb + (u32)((XST + slb*XLD) * 4);

    // ---- issue stage wave 0 ----
    {
        long gb = ((long)(b0 + slb)) * 35;
        #pragma unroll
        for (int j = 0; j < 5; j++){
            int f4 = sq + 8*j;
            if (f4 < 35){
                long gi = gb + f4;
                if (gi < nf4) cp16(sdst_base + (u32)(f4*16), (const float4*)x + gi);
            }
        }
        CP_COMMIT();
    }
    if (tid < 8)  sIdx[tid] = idx[tid];
    if (tid < 5)  sActive[tid] = 0;
    // W1 compacted to 36 rows (structurally-zero obs rows dropped)
    #pragma unroll
    for (int j = 0; j < 5; j++){
        int i = j*BPB + tid;
        if (i < 576){
            int ck = i >> 4, nq = i & 15;
            int o;
            if (ck < 5)       o = ck;
            else if (ck < 11) { int m = (ck-5) >> 1; o = 5 + 3*m + ((ck-5)&1); }
            else              o = 14 + (ck - 11);
            ((float4*)(sm + WRG))[i] = ((const float4*)W1)[o*16 + nq];
        }
    }
    if (tid < 16) ((float4*)(sm + SB1))[tid] = ((const float4*)b1)[tid];
    else if (tid < 32) ((float4*)(sm + SB2))[tid-16] = ((const float4*)b2)[tid-16];
    if (tid < 32){
        int o0 = 2*tid, o1 = 2*tid + 1;
        float x0 = W3[o0*5+1] - W3[o0*5+2], x1 = W3[o1*5+1] - W3[o1*5+2];
        float y0 = W3[o0*5+3] - W3[o0*5+4], y1 = W3[o1*5+3] - W3[o1*5+4];
        ((u64*)(sm + SWDX))[tid] = pack2b(x0, x1);
        ((u64*)(sm + SWDY))[tid] = pack2b(y0, y1);
    }
    if (tid == 0) *(float2*)(sm + SCC) = make_float2(b3[1]-b3[2], b3[3]-b3[4]);

    // obs-build role map: warp-uniform main role, half-warp sub-roles
    const int half = lane >> 4;
    const int olb  = lane & 15;

    // ---- 8 staging waves of 16 batches ----
    #pragma unroll 1
    for (int w = 0; w < 8; w++){
        CP_WAIT0();
        __syncthreads();
        {
            const float* xb = sm + XST + olb*XLD;
            const float p0 = xb[0], p1 = xb[1];
            float* ob = sm + SHR + (w*16 + olb);
            if (wid == 0){
                if (half == 0){
                    ob[0*LDA] = p0;    ob[1*LDA] = p1;    ob[2*LDA] = xb[2];
                    ob[3*LDA] = xb[3]; ob[4*LDA] = xb[4];
                } else {
                    const float* r = xb + (sIdx[7] + 10)*7;   // obstacle 4
                    float dx = r[0]-p0, dy = r[1]-p1;
                    bool in = (dx*dx + dy*dy) < 0.0225f;
                    if (in) sActive[4] = 1;
                    ob[31*LDA] = in ? dx   : 0.0f;
                    ob[32*LDA] = in ? dy   : 0.0f;
                    ob[33*LDA] = in ? r[2] : 0.0f;
                    ob[34*LDA] = in ? r[3] : 0.0f;
                    ob[35*LDA] = in ? r[4] : 0.0f;
                }
            } else if (wid == 1){
                if (half == 0){
                    #pragma unroll
                    for (int m = 0; m < 2; m++){
                        const float* r = xb + sIdx[m]*7;
                        ob[(5+2*m)*LDA] = (r[5] + r[0]) - p0;
                        ob[(6+2*m)*LDA] = (r[6] + r[1]) - p1;
                    }
                } else {
                    const float* r = xb + sIdx[2]*7;
                    ob[9*LDA]  = (r[5] + r[0]) - p0;
                    ob[10*LDA] = (r[6] + r[1]) - p1;
                }
            } else {
                int m = (wid - 2)*2 + half;                   // obstacles 0..3
                const float* r = xb + (sIdx[3+m] + 10)*7;
                float dx = r[0]-p0, dy = r[1]-p1;
                bool in = (dx*dx + dy*dy) < 0.0225f;
                if (in) sActive[m] = 1;
                int kb = 11 + 5*m;
                ob[(kb+0)*LDA] = in ? dx   : 0.0f;
                ob[(kb+1)*LDA] = in ? dy   : 0.0f;
                ob[(kb+2)*LDA] = in ? r[2] : 0.0f;
                ob[(kb+3)*LDA] = in ? r[3] : 0.0f;
                ob[(kb+4)*LDA] = in ? r[4] : 0.0f;
            }
        }
        __syncthreads();
        if (w < 7){
            long gb = ((long)(b0 + (w+1)*16 + slb)) * 35;
            #pragma unroll
            for (int j = 0; j < 5; j++){
                int f4 = sq + 8*j;
                if (f4 < 35){
                    long gi = gb + f4;
                    if (gi < nf4) cp16(sdst_base + (u32)(f4*16), (const float4*)x + gi);
                }
            }
            CP_COMMIT();
        }
    }

    int act0 = sActive[0], act1 = sActive[1], act2 = sActive[2],
        act3 = sActive[3], act4 = sActive[4];

    // ---- GEMM1: [128 x 36] * [36 x 64] ----
    u64 acc[32];
    #pragma unroll
    for (int i = 0; i < 32; i++) acc[i] = 0ull;
    {
        const float* ap = sm + SHR + 4*lane;
        const float* wp = sm + WRG + 16*wid;
        #pragma unroll
        for (int k = 0; k < 11; k++) K_STEP(ap, wp, k);
        if (act0){
            #pragma unroll
            for (int k = 11; k < 16; k++) K_STEP(ap, wp, k);
        }
        if (act1){
            #pragma unroll
            for (int k = 16; k < 21; k++) K_STEP(ap, wp, k);
        }
        if (act2){
            #pragma unroll
            for (int k = 21; k < 26; k++) K_STEP(ap, wp, k);
        }
        if (act3){
            #pragma unroll
            for (int k = 26; k < 31; k++) K_STEP(ap, wp, k);
        }
        if (act4){
            #pragma unroll
            for (int k = 31; k < 36; k++) K_STEP(ap, wp, k);
        }
    }
    __syncthreads();     // W1 + SOBS + XST fully consumed

    // ---- issue W2 over the WRG/XST region ----
    #pragma unroll
    for (int j = 0; j < 8; j++)
        cp16(smb + (u32)((WRG + (j*BPB + tid)*4) * 4), (const float4*)W2 + j*BPB + tid);
    CP_COMMIT();

    // ---- epilogue 1: relu(acc + b1) -> SH1 rows (2 per op-pair) ----
    #pragma unroll
    for (int op = 0; op < 8; op++){
        float bv0 = sm[SB1 + 16*wid + 2*op];
        float bv1 = sm[SB1 + 16*wid + 2*op + 1];
        float2 f0 = unpack2(acc[op]);
        float2 f1 = unpack2(acc[8 + op]);
        float2 f2 = unpack2(acc[16 + op]);
        float2 f3 = unpack2(acc[24 + op]);
        float4 v0, v1;
        v0.x = fmaxf(f0.x + bv0, 0.0f); v0.y = fmaxf(f1.x + bv0, 0.0f);
        v0.z = fmaxf(f2.x + bv0, 0.0f); v0.w = fmaxf(f3.x + bv0, 0.0f);
        v1.x = fmaxf(f0.y + bv1, 0.0f); v1.y = fmaxf(f1.y + bv1, 0.0f);
        v1.z = fmaxf(f2.y + bv1, 0.0f); v1.w = fmaxf(f3.y + bv1, 0.0f);
        *(float4*)(sm + SHR + (16*wid + 2*op    )*LDA + 4*lane) = v0;
        *(float4*)(sm + SHR + (16*wid + 2*op + 1)*LDA + 4*lane) = v1;
    }
    CP_WAIT0();
    __syncthreads();     // SH1 visible + W2 landed

    // ---- GEMM2: [128 x 64] * [64 x 64] ----
    #pragma unroll
    for (int i = 0; i < 32; i++) acc[i] = 0ull;
    {
        const float* ap = sm + SHR + 4*lane;
        const float* wp = sm + WRG + 16*wid;
        #pragma unroll 8
        for (int k = 0; k < 64; k++) K_STEP(ap, wp, k);
    }
    __syncthreads();     // SH1 reads done; SHR free for PF buffer

    // ---- register fold: per batch, packed (x,y) partial over this warp's 16 outputs ----
    {
        u64 px[4], py[4];
        px[0]=px[1]=px[2]=px[3]=0ull;
        py[0]=py[1]=py[2]=py[3]=0ull;
        #pragma unroll
        for (int op = 0; op < 8; op++){
            u64 bv2 = *(const u64*)(sm + SB2 + 16*wid + 2*op);     // packed bias pair
            u64 wx = ((const u64*)(sm + SWDX))[8*wid + op];
            u64 wy = ((const u64*)(sm + SWDY))[8*wid + op];
            #pragma unroll
            for (int b = 0; b < 4; b++){
                float2 f = unpack2(fadd2(acc[b*8 + op], bv2));
                u64 rr = pack2b(fmaxf(f.x, 0.0f), fmaxf(f.y, 0.0f));
                px[b] = ffma2(rr, wx, px[b]);
                py[b] = ffma2(rr, wy, py[b]);
            }
        }
        // partials: pf[wid][batch] = float2(x,y), batch = 4*lane+b
        float2* pfb = (float2*)(sm + SHR);
        #pragma unroll
        for (int b = 0; b < 4; b++){
            float2 fx = unpack2(px[b]);
            float2 fy = unpack2(py[b]);
            pfb[wid*128 + 4*lane + b] = make_float2(fx.x + fx.y, fy.x + fy.y);
        }
    }
    __syncthreads();

    // ---- reduce over 4 warps, scale, clip, store (all 128 threads, one batch each) ----
    {
        const u64* pfu = (const u64*)(sm + SHR);
        u64 a = *(const u64*)(sm + SCC);
        #pragma unroll
        for (int t = 0; t < 4; t++)
            a = fadd2(a, pfu[t*128 + tid]);
        float2 r = unpack2(a);
        float v0 = r.x * 0.1f, v1 = r.y * 0.1f;
        if (fabsf(v0) > 1.0f) v0 = copysignf(2.0f, v0);
        if (fabsf(v1) > 1.0f) v1 = copysignf(2.0f, v1);
        int b = b0 + tid;
        if (b < B) ((float2*)out)[b] = make_float2(v0, v1);
    }
}

extern "C" void kernel_launch(void* const* d_in, const int* in_sizes, int n_in,
                              void* d_out, int out_size)
{
    const float* x  = (const float*)d_in[0];
    const float* W1 = (const float*)d_in[1];
    const float* b1 = (const float*)d_in[2];
    const float* W2 = (const float*)d_in[3];
    const float* b2 = (const float*)d_in[4];
    const float* W3 = (const float*)d_in[5];
    const float* b3 = (const float*)d_in[6];
    const int*  idx = (const int*)d_in[7];

    const int B = in_sizes[0] / 140;
    const int blocks = (B + TILEB - 1) / TILEB;
    const size_t smem = SMEM_FLOATS * sizeof(float);

    cudaFuncSetAttribute(maddpg_v15_kernel,
                         cudaFuncAttributeMaxDynamicSharedMemorySize, (int)smem);

    maddpg_v15_kernel<<<blocks, BPB, smem>>>(x, W1, b1, W2, b2, W3, b3, idx,
                                             (float*)d_out, B);
}

// round 16
// speedup vs baseline: 1.7503x; 1.0295x over previous
#include <cuda_runtime.h>

typedef unsigned int       u32;
typedef unsigned long long u64;

static __device__ __forceinline__ u64 ffma2(u64 a, u64 b, u64 c){
    u64 d; asm("fma.rn.f32x2 %0, %1, %2, %3;" : "=l"(d) : "l"(a), "l"(b), "l"(c)); return d;
}
static __device__ __forceinline__ u64 fadd2(u64 a, u64 b){
    u64 d; asm("add.rn.f32x2 %0, %1, %2;" : "=l"(d) : "l"(a), "l"(b)); return d;
}
static __device__ __forceinline__ u64 pack2(float x){
    u64 r; asm("mov.b64 %0, {%1, %1};" : "=l"(r) : "f"(x)); return r;
}
static __device__ __forceinline__ u64 pack2b(float x, float y){
    u64 r; asm("mov.b64 %0, {%1, %2};" : "=l"(r) : "f"(x), "f"(y)); return r;
}
static __device__ __forceinline__ float2 unpack2(u64 v){
    float lo, hi; asm("mov.b64 {%0, %1}, %2;" : "=f"(lo), "=f"(hi) : "l"(v)); return make_float2(lo, hi);
}
static __device__ __forceinline__ u32 smaddr(const void* p){
    u32 a; asm("{ .reg .u64 t; cvta.to.shared.u64 t, %1; cvt.u32.u64 %0, t; }" : "=r"(a) : "l"(p)); return a;
}
static __device__ __forceinline__ void cp16(u32 dst, const void* src){
    asm volatile("cp.async.cg.shared.global [%0], [%1], 16;" :: "r"(dst), "l"(src));
}
#define CP_COMMIT() asm volatile("cp.async.commit_group;" ::: "memory")
#define CP_WAIT0()  asm volatile("cp.async.wait_group 0;" ::: "memory")

// ---------------- smem layout (float offsets) ----------------
// Staging for a 32-batch wave is SPLIT across two regions that are dead during staging:
//   XSA (batches 0-15):  SHR rows 36+ (floats 4752..7120) — SOBS only uses rows 0-35;
//                        clobbered later by SH1 epilogue (fine, staging done by then).
//   XSB (batches 16-31): 10752..13120 — past W1-compact's end; dead before deferred W2 lands.
#define SHR   0        // SOBS [36][132] / SH1 [64][132] / PF = 8448
#define XSA   4752     // 16 * 148 = 2368 -> ends 7120 (inside SHR upper rows)
#define WRG   8448     // W1 compact (2304 -> ends 10752); W2 (4096 -> 8448..12544) after GEMM1
#define XSB   10752    // 16 * 148 = 2368 -> ends 13120
#define SB1   13120    // 64
#define SB2   13184    // 64
#define SWDX  13248    // 32 u64
#define SWDY  13312    // 32 u64
#define SCC   13376    // float2 (+2 pad)
#define SMEM_FLOATS 13380   // 53520 B -> 4 CTAs/SM

#define BPB   128
#define TILEB 128
#define LDA   132      // SOBS/SH1 row stride
#define XLD   148      // staging row stride (2-way max conflicts on scalar reads)

// one k-step: 4 batch scalars (1 LDS.128 + 4 pack2) x 8 weight-pairs (4 LDS.128, no movs)
// acc[8*b + op] = outputs (2op, 2op+1) for batch 4*lane+b
#define K_STEP(AP, WP, KK) do { \
    float4 a4 = *(const float4*)((AP) + (KK)*LDA); \
    ulonglong2 Wq0 = *(const ulonglong2*)((WP) + (KK)*64); \
    ulonglong2 Wq1 = *(const ulonglong2*)((WP) + (KK)*64 + 4); \
    ulonglong2 Wq2 = *(const ulonglong2*)((WP) + (KK)*64 + 8); \
    ulonglong2 Wq3 = *(const ulonglong2*)((WP) + (KK)*64 + 12); \
    u64 a0 = pack2(a4.x), a1 = pack2(a4.y), a2 = pack2(a4.z), a3 = pack2(a4.w); \
    acc[0]  = ffma2(a0, Wq0.x, acc[0]);  acc[8]  = ffma2(a1, Wq0.x, acc[8]); \
    acc[16] = ffma2(a2, Wq0.x, acc[16]); acc[24] = ffma2(a3, Wq0.x, acc[24]); \
    acc[1]  = ffma2(a0, Wq0.y, acc[1]);  acc[9]  = ffma2(a1, Wq0.y, acc[9]); \
    acc[17] = ffma2(a2, Wq0.y, acc[17]); acc[25] = ffma2(a3, Wq0.y, acc[25]); \
    acc[2]  = ffma2(a0, Wq1.x, acc[2]);  acc[10] = ffma2(a1, Wq1.x, acc[10]); \
    acc[18] = ffma2(a2, Wq1.x, acc[18]); acc[26] = ffma2(a3, Wq1.x, acc[26]); \
    acc[3]  = ffma2(a0, Wq1.y, acc[3]);  acc[11] = ffma2(a1, Wq1.y, acc[11]); \
    acc[19] = ffma2(a2, Wq1.y, acc[19]); acc[27] = ffma2(a3, Wq1.y, acc[27]); \
    acc[4]  = ffma2(a0, Wq2.x, acc[4]);  acc[12] = ffma2(a1, Wq2.x, acc[12]); \
    acc[20] = ffma2(a2, Wq2.x, acc[20]); acc[28] = ffma2(a3, Wq2.x, acc[28]); \
    acc[5]  = ffma2(a0, Wq2.y, acc[5]);  acc[13] = ffma2(a1, Wq2.y, acc[13]); \
    acc[21] = ffma2(a2, Wq2.y, acc[21]); acc[29] = ffma2(a3, Wq2.y, acc[29]); \
    acc[6]  = ffma2(a0, Wq3.x, acc[6]);  acc[14] = ffma2(a1, Wq3.x, acc[14]); \
    acc[22] = ffma2(a2, Wq3.x, acc[22]); acc[30] = ffma2(a3, Wq3.x, acc[30]); \
    acc[7]  = ffma2(a0, Wq3.y, acc[7]);  acc[15] = ffma2(a1, Wq3.y, acc[15]); \
    acc[23] = ffma2(a2, Wq3.y, acc[23]); acc[31] = ffma2(a3, Wq3.y, acc[31]); \
} while(0)

// issue one 32-batch wave; this thread stages batch slb (9 cp16)
#define ISSUE_WAVE(WV) do { \
    long gb = ((long)(b0 + (WV)*32 + slb)) * 35; \
    _Pragma("unroll") \
    for (int j = 0; j < 9; j++){ \
        int f4 = sq + 4*j; \
        if (f4 < 35){ \
            long gi = gb + f4; \
            if (gi < nf4) cp16(sdst_base + (u32)(f4*16), (const float4*)x + gi); \
        } \
    } \
    CP_COMMIT(); \
} while(0)

__global__ __launch_bounds__(BPB, 4) void maddpg_v16_kernel(
    const float* __restrict__ x,
    const float* __restrict__ W1, const float* __restrict__ b1,
    const float* __restrict__ W2, const float* __restrict__ b2,
    const float* __restrict__ W3, const float* __restrict__ b3,
    const int* __restrict__ idx,
    float* __restrict__ out, int B)
{
    extern __shared__ float sm[];
    __shared__ int sIdx[8];
    __shared__ int sActive[5];
    const int tid  = threadIdx.x;
    const int wid  = tid >> 5;       // warp -> output group 16*wid / obs role
    const int lane = tid & 31;       // lane -> batch quad / obs batch
    const u32 smb = smaddr(sm);
    const int b0  = blockIdx.x * TILEB;
    const long nf4 = (long)B * 35;

    // staging map: thread stages batch slb of the 32-batch wave (split regions)
    const int slb = 8*wid + (lane >> 2);
    const int sq  = lane & 3;
    const u32 sdst_base = smb + (u32)(((slb < 16 ? XSA + slb*XLD
                                                 : XSB + (slb-16)*XLD)) * 4);
    // obs-build read base for this lane's batch
    const float* xb = sm + (lane < 16 ? XSA + lane*XLD : XSB + (lane-16)*XLD);

    // ---- issue stage wave 0 ----
    ISSUE_WAVE(0);
    if (tid < 8)  sIdx[tid] = idx[tid];
    if (tid < 5)  sActive[tid] = 0;
    // W1 compacted to 36 rows (structurally-zero obs rows dropped)
    #pragma unroll
    for (int j = 0; j < 5; j++){
        int i = j*BPB + tid;
        if (i < 576){
            int ck = i >> 4, nq = i & 15;
            int o;
            if (ck < 5)       o = ck;
            else if (ck < 11) { int m = (ck-5) >> 1; o = 5 + 3*m + ((ck-5)&1); }
            else              o = 14 + (ck - 11);
            ((float4*)(sm + WRG))[i] = ((const float4*)W1)[o*16 + nq];
        }
    }
    if (tid < 16) ((float4*)(sm + SB1))[tid] = ((const float4*)b1)[tid];
    else if (tid < 32) ((float4*)(sm + SB2))[tid-16] = ((const float4*)b2)[tid-16];
    if (tid < 32){
        int o0 = 2*tid, o1 = 2*tid + 1;
        float x0 = W3[o0*5+1] - W3[o0*5+2], x1 = W3[o1*5+1] - W3[o1*5+2];
        float y0 = W3[o0*5+3] - W3[o0*5+4], y1 = W3[o1*5+3] - W3[o1*5+4];
        ((u64*)(sm + SWDX))[tid] = pack2b(x0, x1);
        ((u64*)(sm + SWDY))[tid] = pack2b(y0, y1);
    }
    if (tid == 0) *(float2*)(sm + SCC) = make_float2(b3[1]-b3[2], b3[3]-b3[4]);

    // ---- 4 staging waves of 32 batches; obs role = warp (uniform), batch = lane ----
    #pragma unroll 1
    for (int w = 0; w < 4; w++){
        CP_WAIT0();
        __syncthreads();
        {
            const float p0 = xb[0], p1 = xb[1];
            float* ob = sm + SHR + (w*32 + lane);   // column; lane-consecutive STS
            if (wid == 0){
                ob[0*LDA] = p0;    ob[1*LDA] = p1;    ob[2*LDA] = xb[2];
                ob[3*LDA] = xb[3]; ob[4*LDA] = xb[4];
                const float* r = xb + (sIdx[7] + 10)*7;       // obstacle 4
                float dx = r[0]-p0, dy = r[1]-p1;
                bool in = (dx*dx + dy*dy) < 0.0225f;
                if (in) sActive[4] = 1;
                ob[31*LDA] = in ? dx   : 0.0f;
                ob[32*LDA] = in ? dy   : 0.0f;
                ob[33*LDA] = in ? r[2] : 0.0f;
                ob[34*LDA] = in ? r[3] : 0.0f;
                ob[35*LDA] = in ? r[4] : 0.0f;
            } else if (wid == 1){
                #pragma unroll
                for (int m = 0; m < 3; m++){
                    const float* r = xb + sIdx[m]*7;
                    ob[(5+2*m)*LDA] = (r[5] + r[0]) - p0;
                    ob[(6+2*m)*LDA] = (r[6] + r[1]) - p1;
                }
            } else {
                #pragma unroll
                for (int mm = 0; mm < 2; mm++){
                    int m = (wid-2)*2 + mm;                   // obstacles 0..3
                    const float* r = xb + (sIdx[3+m] + 10)*7;
                    float dx = r[0]-p0, dy = r[1]-p1;
                    bool in = (dx*dx + dy*dy) < 0.0225f;
                    if (in) sActive[m] = 1;
                    int kb = 11 + 5*m;
                    ob[(kb+0)*LDA] = in ? dx   : 0.0f;
                    ob[(kb+1)*LDA] = in ? dy   : 0.0f;
                    ob[(kb+2)*LDA] = in ? r[2] : 0.0f;
                    ob[(kb+3)*LDA] = in ? r[3] : 0.0f;
                    ob[(kb+4)*LDA] = in ? r[4] : 0.0f;
                }
            }
        }
        __syncthreads();     // buffers consumed; safe to refill
        if (w < 3) ISSUE_WAVE(w+1);
    }

    int act0 = sActive[0], act1 = sActive[1], act2 = sActive[2],
        act3 = sActive[3], act4 = sActive[4];

    // ---- GEMM1: [128 x 36] * [36 x 64] ----
    u64 acc[32];
    #pragma unroll
    for (int i = 0; i < 32; i++) acc[i] = 0ull;
    {
        const float* ap = sm + SHR + 4*lane;
        const float* wp = sm + WRG + 16*wid;
        #pragma unroll
        for (int k = 0; k < 11; k++) K_STEP(ap, wp, k);
        if (act0){
            #pragma unroll
            for (int k = 11; k < 16; k++) K_STEP(ap, wp, k);
        }
        if (act1){
            #pragma unroll
            for (int k = 16; k < 21; k++) K_STEP(ap, wp, k);
        }
        if (act2){
            #pragma unroll
            for (int k = 21; k < 26; k++) K_STEP(ap, wp, k);
        }
        if (act3){
            #pragma unroll
            for (int k = 26; k < 31; k++) K_STEP(ap, wp, k);
        }
        if (act4){
            #pragma unroll
            for (int k = 31; k < 36; k++) K_STEP(ap, wp, k);
        }
    }
    __syncthreads();     // W1 + SOBS + staging regions fully consumed

    // ---- issue W2 over WRG/XSB ----
    #pragma unroll
    for (int j = 0; j < 8; j++)
        cp16(smb + (u32)((WRG + (j*BPB + tid)*4) * 4), (const float4*)W2 + j*BPB + tid);
    CP_COMMIT();

    // ---- epilogue 1: relu(acc + b1) -> SH1 rows ----
    #pragma unroll
    for (int op = 0; op < 8; op++){
        float bv0 = sm[SB1 + 16*wid + 2*op];
        float bv1 = sm[SB1 + 16*wid + 2*op + 1];
        float2 f0 = unpack2(acc[op]);
        float2 f1 = unpack2(acc[8 + op]);
        float2 f2 = unpack2(acc[16 + op]);
        float2 f3 = unpack2(acc[24 + op]);
        float4 v0, v1;
        v0.x = fmaxf(f0.x + bv0, 0.0f); v0.y = fmaxf(f1.x + bv0, 0.0f);
        v0.z = fmaxf(f2.x + bv0, 0.0f); v0.w = fmaxf(f3.x + bv0, 0.0f);
        v1.x = fmaxf(f0.y + bv1, 0.0f); v1.y = fmaxf(f1.y + bv1, 0.0f);
        v1.z = fmaxf(f2.y + bv1, 0.0f); v1.w = fmaxf(f3.y + bv1, 0.0f);
        *(float4*)(sm + SHR + (16*wid + 2*op    )*LDA + 4*lane) = v0;
        *(float4*)(sm + SHR + (16*wid + 2*op + 1)*LDA + 4*lane) = v1;
    }
    CP_WAIT0();
    __syncthreads();     // SH1 visible + W2 landed

    // ---- GEMM2: [128 x 64] * [64 x 64] ----
    #pragma unroll
    for (int i = 0; i < 32; i++) acc[i] = 0ull;
    {
        const float* ap = sm + SHR + 4*lane;
        const float* wp = sm + WRG + 16*wid;
        #pragma unroll 8
        for (int k = 0; k < 64; k++) K_STEP(ap, wp, k);
    }
    __syncthreads();     // SH1 reads done; SHR free for PF buffer

    // ---- register fold: per batch, packed (x,y) partial over this warp's 16 outputs ----
    {
        u64 px[4], py[4];
        px[0]=px[1]=px[2]=px[3]=0ull;
        py[0]=py[1]=py[2]=py[3]=0ull;
        #pragma unroll
        for (int op = 0; op < 8; op++){
            u64 bv2 = *(const u64*)(sm + SB2 + 16*wid + 2*op);
            u64 wx = ((const u64*)(sm + SWDX))[8*wid + op];
            u64 wy = ((const u64*)(sm + SWDY))[8*wid + op];
            #pragma unroll
            for (int b = 0; b < 4; b++){
                float2 f = unpack2(fadd2(acc[b*8 + op], bv2));
                u64 rr = pack2b(fmaxf(f.x, 0.0f), fmaxf(f.y, 0.0f));
                px[b] = ffma2(rr, wx, px[b]);
                py[b] = ffma2(rr, wy, py[b]);
            }
        }
        float2* pfb = (float2*)(sm + SHR);
        #pragma unroll
        for (int b = 0; b < 4; b++){
            float2 fx = unpack2(px[b]);
            float2 fy = unpack2(py[b]);
            pfb[wid*128 + 4*lane + b] = make_float2(fx.x + fx.y, fy.x + fy.y);
        }
    }
    __syncthreads();

    // ---- reduce over 4 warps, scale, clip, store ----
    {
        const u64* pfu = (const u64*)(sm + SHR);
        u64 a = *(const u64*)(sm + SCC);
        #pragma unroll
        for (int t = 0; t < 4; t++)
            a = fadd2(a, pfu[t*128 + tid]);
        float2 r = unpack2(a);
        float v0 = r.x * 0.1f, v1 = r.y * 0.1f;
        if (fabsf(v0) > 1.0f) v0 = copysignf(2.0f, v0);
        if (fabsf(v1) > 1.0f) v1 = copysignf(2.0f, v1);
        int b = b0 + tid;
        if (b < B) ((float2*)out)[b] = make_float2(v0, v1);
    }
}

extern "C" void kernel_launch(void* const* d_in, const int* in_sizes, int n_in,
                              void* d_out, int out_size)
{
    const float* x  = (const float*)d_in[0];
    const float* W1 = (const float*)d_in[1];
    const float* b1 = (const float*)d_in[2];
    const float* W2 = (const float*)d_in[3];
    const float* b2 = (const float*)d_in[4];
    const float* W3 = (const float*)d_in[5];
    const float* b3 = (const float*)d_in[6];
    const int*  idx = (const int*)d_in[7];

    const int B = in_sizes[0] / 140;
    const int blocks = (B + TILEB - 1) / TILEB;
    const size_t smem = SMEM_FLOATS * sizeof(float);

    cudaFuncSetAttribute(maddpg_v16_kernel,
                         cudaFuncAttributeMaxDynamicSharedMemorySize, (int)smem);

    maddpg_v16_kernel<<<blocks, BPB, smem>>>(x, W1, b1, W2, b2, W3, b3, idx,
                                             (float*)d_out, B);
}

// round 17
// speedup vs baseline: 1.7507x; 1.0002x over previous
#include <cuda_runtime.h>

typedef unsigned int       u32;
typedef unsigned long long u64;

static __device__ __forceinline__ u64 ffma2(u64 a, u64 b, u64 c){
    u64 d; asm("fma.rn.f32x2 %0, %1, %2, %3;" : "=l"(d) : "l"(a), "l"(b), "l"(c)); return d;
}
static __device__ __forceinline__ u64 fadd2(u64 a, u64 b){
    u64 d; asm("add.rn.f32x2 %0, %1, %2;" : "=l"(d) : "l"(a), "l"(b)); return d;
}
static __device__ __forceinline__ u64 pack2(float x){
    u64 r; asm("mov.b64 %0, {%1, %1};" : "=l"(r) : "f"(x)); return r;
}
static __device__ __forceinline__ u64 pack2b(float x, float y){
    u64 r; asm("mov.b64 %0, {%1, %2};" : "=l"(r) : "f"(x), "f"(y)); return r;
}
static __device__ __forceinline__ float2 unpack2(u64 v){
    float lo, hi; asm("mov.b64 {%0, %1}, %2;" : "=f"(lo), "=f"(hi) : "l"(v)); return make_float2(lo, hi);
}
static __device__ __forceinline__ u32 smaddr(const void* p){
    u32 a; asm("{ .reg .u64 t; cvta.to.shared.u64 t, %1; cvt.u32.u64 %0, t; }" : "=r"(a) : "l"(p)); return a;
}
static __device__ __forceinline__ void cp16(u32 dst, const void* src){
    asm volatile("cp.async.cg.shared.global [%0], [%1], 16;" :: "r"(dst), "l"(src));
}
#define CP_COMMIT() asm volatile("cp.async.commit_group;" ::: "memory")
#define CP_WAIT0()  asm volatile("cp.async.wait_group 0;" ::: "memory")

// ---------------- smem layout (float offsets) ----------------
#define SHR   0        // SOBS [36][132] / SH1 [64][132] / PF = 8448
#define XSA   4752     // 16 * 148 = 2368 (inside SHR upper rows, dead during staging)
#define WRG   8448     // W1 compact (2304) -> W2 (4096) after GEMM1
#define XSB   10752    // 16 * 148 = 2368 (past W1; dead before deferred W2 lands)
#define SB1   13120    // 64
#define SB2   13184    // 64
#define SWDX  13248    // 32 u64
#define SWDY  13312    // 32 u64
#define SCC   13376    // float2 (+2 pad)
#define SMEM_FLOATS 13380   // 53520 B -> 4 CTAs/SM

#define BPB   128
#define TILEB 128
#define LDA   132
#define XLD   148

// FFMA body given a4 (activation float4) and k for weight loads
#define K_BODY(A4, WP, KK) do { \
    ulonglong2 Wq0 = *(const ulonglong2*)((WP) + (KK)*64); \
    ulonglong2 Wq1 = *(const ulonglong2*)((WP) + (KK)*64 + 4); \
    ulonglong2 Wq2 = *(const ulonglong2*)((WP) + (KK)*64 + 8); \
    ulonglong2 Wq3 = *(const ulonglong2*)((WP) + (KK)*64 + 12); \
    u64 a0 = pack2((A4).x), a1 = pack2((A4).y), a2 = pack2((A4).z), a3 = pack2((A4).w); \
    acc[0]  = ffma2(a0, Wq0.x, acc[0]);  acc[8]  = ffma2(a1, Wq0.x, acc[8]); \
    acc[16] = ffma2(a2, Wq0.x, acc[16]); acc[24] = ffma2(a3, Wq0.x, acc[24]); \
    acc[1]  = ffma2(a0, Wq0.y, acc[1]);  acc[9]  = ffma2(a1, Wq0.y, acc[9]); \
    acc[17] = ffma2(a2, Wq0.y, acc[17]); acc[25] = ffma2(a3, Wq0.y, acc[25]); \
    acc[2]  = ffma2(a0, Wq1.x, acc[2]);  acc[10] = ffma2(a1, Wq1.x, acc[10]); \
    acc[18] = ffma2(a2, Wq1.x, acc[18]); acc[26] = ffma2(a3, Wq1.x, acc[26]); \
    acc[3]  = ffma2(a0, Wq1.y, acc[3]);  acc[11] = ffma2(a1, Wq1.y, acc[11]); \
    acc[19] = ffma2(a2, Wq1.y, acc[19]); acc[27] = ffma2(a3, Wq1.y, acc[27]); \
    acc[4]  = ffma2(a0, Wq2.x, acc[4]);  acc[12] = ffma2(a1, Wq2.x, acc[12]); \
    acc[20] = ffma2(a2, Wq2.x, acc[20]); acc[28] = ffma2(a3, Wq2.x, acc[28]); \
    acc[5]  = ffma2(a0, Wq2.y, acc[5]);  acc[13] = ffma2(a1, Wq2.y, acc[13]); \
    acc[21] = ffma2(a2, Wq2.y, acc[21]); acc[29] = ffma2(a3, Wq2.y, acc[29]); \
    acc[6]  = ffma2(a0, Wq3.x, acc[6]);  acc[14] = ffma2(a1, Wq3.x, acc[14]); \
    acc[22] = ffma2(a2, Wq3.x, acc[22]); acc[30] = ffma2(a3, Wq3.x, acc[30]); \
    acc[7]  = ffma2(a0, Wq3.y, acc[7]);  acc[15] = ffma2(a1, Wq3.y, acc[15]); \
    acc[23] = ffma2(a2, Wq3.y, acc[23]); acc[31] = ffma2(a3, Wq3.y, acc[31]); \
} while(0)

#define K_STEP(AP, WP, KK) do { \
    float4 a4 = *(const float4*)((AP) + (KK)*LDA); \
    K_BODY(a4, WP, KK); \
} while(0)

#define ISSUE_WAVE(WV) do { \
    long gb = ((long)(b0 + (WV)*32 + slb)) * 35; \
    _Pragma("unroll") \
    for (int j = 0; j < 9; j++){ \
        int f4 = sq + 4*j; \
        if (f4 < 35){ \
            long gi = gb + f4; \
            if (gi < nf4) cp16(sdst_base + (u32)(f4*16), (const float4*)x + gi); \
        } \
    } \
    CP_COMMIT(); \
} while(0)

__global__ __launch_bounds__(BPB, 4) void maddpg_v17_kernel(
    const float* __restrict__ x,
    const float* __restrict__ W1, const float* __restrict__ b1,
    const float* __restrict__ W2, const float* __restrict__ b2,
    const float* __restrict__ W3, const float* __restrict__ b3,
    const int* __restrict__ idx,
    float* __restrict__ out, int B)
{
    extern __shared__ float sm[];
    __shared__ int sIdx[8];
    __shared__ int sActive[5];
    const int tid  = threadIdx.x;
    const int wid  = tid >> 5;
    const int lane = tid & 31;
    const u32 smb = smaddr(sm);
    const int b0  = blockIdx.x * TILEB;
    const long nf4 = (long)B * 35;

    const int slb = 8*wid + (lane >> 2);
    const int sq  = lane & 3;
    const u32 sdst_base = smb + (u32)(((slb < 16 ? XSA + slb*XLD
                                                 : XSB + (slb-16)*XLD)) * 4);
    const float* xb = sm + (lane < 16 ? XSA + lane*XLD : XSB + (lane-16)*XLD);

    ISSUE_WAVE(0);
    if (tid < 8)  sIdx[tid] = idx[tid];
    if (tid < 5)  sActive[tid] = 0;
    #pragma unroll
    for (int j = 0; j < 5; j++){
        int i = j*BPB + tid;
        if (i < 576){
            int ck = i >> 4, nq = i & 15;
            int o;
            if (ck < 5)       o = ck;
            else if (ck < 11) { int m = (ck-5) >> 1; o = 5 + 3*m + ((ck-5)&1); }
            else              o = 14 + (ck - 11);
            ((float4*)(sm + WRG))[i] = ((const float4*)W1)[o*16 + nq];
        }
    }
    if (tid < 16) ((float4*)(sm + SB1))[tid] = ((const float4*)b1)[tid];
    else if (tid < 32) ((float4*)(sm + SB2))[tid-16] = ((const float4*)b2)[tid-16];
    if (tid < 32){
        int o0 = 2*tid, o1 = 2*tid + 1;
        float x0 = W3[o0*5+1] - W3[o0*5+2], x1 = W3[o1*5+1] - W3[o1*5+2];
        float y0 = W3[o0*5+3] - W3[o0*5+4], y1 = W3[o1*5+3] - W3[o1*5+4];
        ((u64*)(sm + SWDX))[tid] = pack2b(x0, x1);
        ((u64*)(sm + SWDY))[tid] = pack2b(y0, y1);
    }
    if (tid == 0) *(float2*)(sm + SCC) = make_float2(b3[1]-b3[2], b3[3]-b3[4]);

    // ---- 4 staging waves of 32 batches; obs role = warp, batch = lane ----
    #pragma unroll 1
    for (int w = 0; w < 4; w++){
        CP_WAIT0();
        __syncthreads();
        {
            const float p0 = xb[0], p1 = xb[1];
            float* ob = sm + SHR + (w*32 + lane);
            if (wid == 0){
                ob[0*LDA] = p0;    ob[1*LDA] = p1;    ob[2*LDA] = xb[2];
                ob[3*LDA] = xb[3]; ob[4*LDA] = xb[4];
                const float* r = xb + (sIdx[7] + 10)*7;
                float dx = r[0]-p0, dy = r[1]-p1;
                bool in = (dx*dx + dy*dy) < 0.0225f;
                if (in) sActive[4] = 1;
                ob[31*LDA] = in ? dx   : 0.0f;
                ob[32*LDA] = in ? dy   : 0.0f;
                ob[33*LDA] = in ? r[2] : 0.0f;
                ob[34*LDA] = in ? r[3] : 0.0f;
                ob[35*LDA] = in ? r[4] : 0.0f;
            } else if (wid == 1){
                #pragma unroll
                for (int m = 0; m < 3; m++){
                    const float* r = xb + sIdx[m]*7;
                    ob[(5+2*m)*LDA] = (r[5] + r[0]) - p0;
                    ob[(6+2*m)*LDA] = (r[6] + r[1]) - p1;
                }
            } else {
                #pragma unroll
                for (int mm = 0; mm < 2; mm++){
                    int m = (wid-2)*2 + mm;
                    const float* r = xb + (sIdx[3+m] + 10)*7;
                    float dx = r[0]-p0, dy = r[1]-p1;
                    bool in = (dx*dx + dy*dy) < 0.0225f;
                    if (in) sActive[m] = 1;
                    int kb = 11 + 5*m;
                    ob[(kb+0)*LDA] = in ? dx   : 0.0f;
                    ob[(kb+1)*LDA] = in ? dy   : 0.0f;
                    ob[(kb+2)*LDA] = in ? r[2] : 0.0f;
                    ob[(kb+3)*LDA] = in ? r[3] : 0.0f;
                    ob[(kb+4)*LDA] = in ? r[4] : 0.0f;
                }
            }
        }
        __syncthreads();
        if (w < 3) ISSUE_WAVE(w+1);
    }

    int act0 = sActive[0], act1 = sActive[1], act2 = sActive[2],
        act3 = sActive[3], act4 = sActive[4];

    // ---- GEMM1 ----
    u64 acc[32];
    #pragma unroll
    for (int i = 0; i < 32; i++) acc[i] = 0ull;
    {
        const float* ap = sm + SHR + 4*lane;
        const float* wp = sm + WRG + 16*wid;
        #pragma unroll
        for (int k = 0; k < 11; k++) K_STEP(ap, wp, k);
        if (act0){
            #pragma unroll
            for (int k = 11; k < 16; k++) K_STEP(ap, wp, k);
        }
        if (act1){
            #pragma unroll
            for (int k = 16; k < 21; k++) K_STEP(ap, wp, k);
        }
        if (act2){
            #pragma unroll
            for (int k = 21; k < 26; k++) K_STEP(ap, wp, k);
        }
        if (act3){
            #pragma unroll
            for (int k = 26; k < 31; k++) K_STEP(ap, wp, k);
        }
        if (act4){
            #pragma unroll
            for (int k = 31; k < 36; k++) K_STEP(ap, wp, k);
        }
    }
    __syncthreads();

    // ---- issue W2 over WRG/XSB ----
    #pragma unroll
    for (int j = 0; j < 8; j++)
        cp16(smb + (u32)((WRG + (j*BPB + tid)*4) * 4), (const float4*)W2 + j*BPB + tid);
    CP_COMMIT();

    // ---- epilogue 1 ----
    #pragma unroll
    for (int op = 0; op < 8; op++){
        float bv0 = sm[SB1 + 16*wid + 2*op];
        float bv1 = sm[SB1 + 16*wid + 2*op + 1];
        float2 f0 = unpack2(acc[op]);
        float2 f1 = unpack2(acc[8 + op]);
        float2 f2 = unpack2(acc[16 + op]);
        float2 f3 = unpack2(acc[24 + op]);
        float4 v0, v1;
        v0.x = fmaxf(f0.x + bv0, 0.0f); v0.y = fmaxf(f1.x + bv0, 0.0f);
        v0.z = fmaxf(f2.x + bv0, 0.0f); v0.w = fmaxf(f3.x + bv0, 0.0f);
        v1.x = fmaxf(f0.y + bv1, 0.0f); v1.y = fmaxf(f1.y + bv1, 0.0f);
        v1.z = fmaxf(f2.y + bv1, 0.0f); v1.w = fmaxf(f3.y + bv1, 0.0f);
        *(float4*)(sm + SHR + (16*wid + 2*op    )*LDA + 4*lane) = v0;
        *(float4*)(sm + SHR + (16*wid + 2*op + 1)*LDA + 4*lane) = v1;
    }
    CP_WAIT0();
    __syncthreads();

    // ---- GEMM2 with A-prefetch software pipeline, unroll 16 ----
    #pragma unroll
    for (int i = 0; i < 32; i++) acc[i] = 0ull;
    {
        const float* ap = sm + SHR + 4*lane;
        const float* wp = sm + WRG + 16*wid;
        float4 a_next = *(const float4*)(ap);
        #pragma unroll 16
        for (int k = 0; k < 64; k++){
            float4 a_cur = a_next;
            if (k < 63) a_next = *(const float4*)(ap + (k+1)*LDA);
            K_BODY(a_cur, wp, k);
        }
    }
    __syncthreads();

    // ---- register fold ----
    {
        u64 px[4], py[4];
        px[0]=px[1]=px[2]=px[3]=0ull;
        py[0]=py[1]=py[2]=py[3]=0ull;
        #pragma unroll
        for (int op = 0; op < 8; op++){
            u64 bv2 = *(const u64*)(sm + SB2 + 16*wid + 2*op);
            u64 wx = ((const u64*)(sm + SWDX))[8*wid + op];
            u64 wy = ((const u64*)(sm + SWDY))[8*wid + op];
            #pragma unroll
            for (int b = 0; b < 4; b++){
                float2 f = unpack2(fadd2(acc[b*8 + op], bv2));
                u64 rr = pack2b(fmaxf(f.x, 0.0f), fmaxf(f.y, 0.0f));
                px[b] = ffma2(rr, wx, px[b]);
                py[b] = ffma2(rr, wy, py[b]);
            }
        }
        float2* pfb = (float2*)(sm + SHR);
        #pragma unroll
        for (int b = 0; b < 4; b++){
            float2 fx = unpack2(px[b]);
            float2 fy = unpack2(py[b]);
            pfb[wid*128 + 4*lane + b] = make_float2(fx.x + fx.y, fy.x + fy.y);
        }
    }
    __syncthreads();

    // ---- reduce, scale, clip, store ----
    {
        const u64* pfu = (const u64*)(sm + SHR);
        u64 a = *(const u64*)(sm + SCC);
        #pragma unroll
        for (int t = 0; t < 4; t++)
            a = fadd2(a, pfu[t*128 + tid]);
        float2 r = unpack2(a);
        float v0 = r.x * 0.1f, v1 = r.y * 0.1f;
        if (fabsf(v0) > 1.0f) v0 = copysignf(2.0f, v0);
        if (fabsf(v1) > 1.0f) v1 = copysignf(2.0f, v1);
        int b = b0 + tid;
        if (b < B) ((float2*)out)[b] = make_float2(v0, v1);
    }
}

extern "C" void kernel_launch(void* const* d_in, const int* in_sizes, int n_in,
                              void* d_out, int out_size)
{
    const float* x  = (const float*)d_in[0];
    const float* W1 = (const float*)d_in[1];
    const float* b1 = (const float*)d_in[2];
    const float* W2 = (const float*)d_in[3];
    const float* b2 = (const float*)d_in[4];
    const float* W3 = (const float*)d_in[5];
    const float* b3 = (const float*)d_in[6];
    const int*  idx = (const int*)d_in[7];

    const int B = in_sizes[0] / 140;
    const int blocks = (B + TILEB - 1) / TILEB;
    const size_t smem = SMEM_FLOATS * sizeof(float);

    cudaFuncSetAttribute(maddpg_v17_kernel,
                         cudaFuncAttributeMaxDynamicSharedMemorySize, (int)smem);

    maddpg_v17_kernel<<<blocks, BPB, smem>>>(x, W1, b1, W2, b2, W3, b3, idx,
                                             (float*)d_out, B);
}